// round 5
// baseline (speedup 1.0000x reference)
#include <cuda_runtime.h>
#include <cuda_bf16.h>
#include <cstdint>

#define HW 4096
#define B_ 8

// ---------------- scratch -----------------------------------------------------
__device__ float d_qkvT[(size_t)B_ * HW * 1024];   // pixel-major: [b][p][ch] q0-255,k256-511,v512-1023
__device__ float d_ssqp[4 * B_ * HW];              // partial ssq tiles q0,q1,k0,k1
__device__ float d_invq[B_ * HW];
__device__ float d_invk[B_ * HW];
__device__ float d_kvpart[64 * 8 * 2048];
__device__ float d_m[64 * 32];
__device__ float d_gate[64 * HW];
__device__ float d_ball[1024];
__device__ float d_s[256];
__device__ float d_t[256];
__device__ __nv_bfloat16 d_Wq_h[1024 * 256], d_Wq_l[1024 * 256];
__device__ __nv_bfloat16 d_xT_h[(size_t)B_ * HW * 256], d_xT_l[(size_t)B_ * HW * 256];
__device__ __nv_bfloat16 d_W2_h[B_ * 256 * 256], d_W2_l[B_ * 256 * 256];

// ---------------- helpers (sm_80-baseline PTX only) ----------------------------
__device__ __forceinline__ uint32_t smem_u32(const void* p) {
    uint32_t a;
    asm("{ .reg .u64 t; cvta.to.shared.u64 t, %1; cvt.u32.u64 %0, t; }" : "=r"(a) : "l"(p));
    return a;
}
__device__ __forceinline__ void cp16(uint32_t dst, const void* src) {
    asm volatile("cp.async.cg.shared.global [%0], [%1], 16;" :: "r"(dst), "l"(src));
}
#define CP_COMMIT() asm volatile("cp.async.commit_group;" ::: "memory")

__device__ __forceinline__ void ldsm4(uint32_t* r, uint32_t addr) {
    asm volatile("ldmatrix.sync.aligned.m8n8.x4.shared.b16 {%0,%1,%2,%3}, [%4];"
        : "=r"(r[0]), "=r"(r[1]), "=r"(r[2]), "=r"(r[3]) : "r"(addr));
}
__device__ __forceinline__ void mma16816(float* d, const uint32_t* a, uint32_t b0, uint32_t b1) {
    asm volatile("mma.sync.aligned.m16n8k16.row.col.f32.bf16.bf16.f32 "
        "{%0,%1,%2,%3}, {%4,%5,%6,%7}, {%8,%9}, {%0,%1,%2,%3};"
        : "+f"(d[0]), "+f"(d[1]), "+f"(d[2]), "+f"(d[3])
        : "r"(a[0]), "r"(a[1]), "r"(a[2]), "r"(a[3]), "r"(b0), "r"(b1));
}

// ---------------- K0: pack weights hi/lo, biases, BN fold ----------------------
__global__ void k0_prep(const float* __restrict__ Wq, const float* __restrict__ bq,
                        const float* __restrict__ Wk, const float* __restrict__ bk,
                        const float* __restrict__ Wv, const float* __restrict__ bv,
                        const float* __restrict__ bf,
                        const float* __restrict__ gamma, const float* __restrict__ beta,
                        const float* __restrict__ mean,  const float* __restrict__ var) {
    int idx = blockIdx.x * blockDim.x + threadIdx.x;
    if (idx < 1024 * 256) {
        int r = idx >> 8, c = idx & 255;
        float w = (r < 256) ? Wq[r * 256 + c] : (r < 512) ? Wk[(r - 256) * 256 + c] : Wv[(r - 512) * 256 + c];
        __nv_bfloat16 h = __float2bfloat16(w);
        d_Wq_h[idx] = h;
        d_Wq_l[idx] = __float2bfloat16(w - __bfloat162float(h));
    }
    if (idx < 1024)
        d_ball[idx] = (idx < 256) ? bq[idx] : (idx < 512) ? bk[idx - 256] : bv[idx - 512];
    if (idx < 256) {
        float s = gamma[idx] * rsqrtf(var[idx] + 1e-5f);
        d_s[idx] = s;
        d_t[idx] = (bf[idx] - mean[idx]) * s + beta[idx];
    }
}

// ---------------- convert x -> xT hi/lo (transpose + split, bf16x2 stores) -----
__global__ __launch_bounds__(256) void k_convx(const float* __restrict__ x) {
    __shared__ float t[64][33];
    int p0 = blockIdx.x * 32, c0 = blockIdx.y * 64, b = blockIdx.z;
    const float* src = x + ((size_t)b * 256 + c0) * HW + p0;
    int tid = threadIdx.x;
#pragma unroll
    for (int j = 0; j < 8; j++) {
        int idx = tid + j * 256;
        int cc = idx >> 5, pp = idx & 31;
        t[cc][pp] = src[(size_t)cc * HW + pp];
    }
    __syncthreads();
    __nv_bfloat162* oh = (__nv_bfloat162*)d_xT_h;
    __nv_bfloat162* ol = (__nv_bfloat162*)d_xT_l;
#pragma unroll
    for (int j = 0; j < 4; j++) {
        int idx = tid + j * 256;
        int p = idx >> 5, pr = idx & 31;
        float v0 = t[pr * 2][p], v1 = t[pr * 2 + 1][p];
        __nv_bfloat16 h0 = __float2bfloat16(v0), h1 = __float2bfloat16(v1);
        __nv_bfloat162 hh; hh.x = h0; hh.y = h1;
        __nv_bfloat162 ll;
        ll.x = __float2bfloat16(v0 - __bfloat162float(h0));
        ll.y = __float2bfloat16(v1 - __bfloat162float(h1));
        size_t o = ((size_t)b * HW + p0 + p) * 128 + (c0 >> 1) + pr;
        oh[o] = hh;
        ol[o] = ll;
    }
}

// ---------------- mma.sync GEMM ------------------------------------------------
// MODE 0: qkv = Wqkv @ x^T  -> writes d_qkvT transposed + partial ssq
// MODE 1: out = Wf2 @ z^T   -> B operand (z = gate*invq*q) folded in loader
// Block 128x128, 8 warps (2x4), warp tile 64x32, K-chunk 32, 3-stage cp.async,
// single __syncthreads per iteration.
#define PITCH 80
#define TILE_BYTES (128 * PITCH)
#define SM_TILE(s, t) (((s) * 4 + (t)) * TILE_BYTES)
#define SMEM_SZ (12 * TILE_BYTES)

template <int MODE>
__global__ __launch_bounds__(256, 1) void k_mma(float* __restrict__ CoutExt) {
    extern __shared__ char smem[];
    uint32_t sb = smem_u32(smem);
    const int tid = threadIdx.x;
    const int lane = tid & 31;
    const int wid = tid >> 5;
    const int wm = wid >> 2, wn = wid & 3;
    const int m0w = wm * 64, n0w = wn * 32;
    const int b = blockIdx.z;
    const int nbase = blockIdx.x * 128;
    const int mbase = blockIdx.y * 128;

    const __nv_bfloat16* Ah = (MODE == 0) ? d_Wq_h + (size_t)mbase * 256
                                          : d_W2_h + (size_t)b * 65536 + (size_t)mbase * 256;
    const __nv_bfloat16* Al = (MODE == 0) ? d_Wq_l + (size_t)mbase * 256
                                          : d_W2_l + (size_t)b * 65536 + (size_t)mbase * 256;
    const __nv_bfloat16* Bh = d_xT_h + (size_t)b * HW * 256 + (size_t)nbase * 256;
    const __nv_bfloat16* Bl = d_xT_l + (size_t)b * HW * 256 + (size_t)nbase * 256;

    const __nv_bfloat16* bases4[4] = {Ah, Al, Bh, Bl};
    const __nv_bfloat16* bases2[2] = {Ah, Al};

    auto load4 = [&](int kc, int s) {
#pragma unroll
        for (int j = 0; j < 8; j++) {
            int g = tid + j * 256;
            int t = g >> 9, w = g & 511;
            int r = w >> 2, c = w & 3;
            const char* src = (const char*)bases4[t] + ((size_t)r * 256 + kc * 32 + c * 8) * 2;
            cp16(sb + SM_TILE(s, t) + r * PITCH + c * 16, src);
        }
        CP_COMMIT();
    };
    auto loadA = [&](int kc, int s) {
#pragma unroll
        for (int j = 0; j < 4; j++) {
            int g = tid + j * 256;
            int t = g >> 9, w = g & 511;
            int r = w >> 2, c = w & 3;
            const char* src = (const char*)bases2[t] + ((size_t)r * 256 + kc * 32 + c * 8) * 2;
            cp16(sb + SM_TILE(s, t) + r * PITCH + c * 16, src);
        }
        CP_COMMIT();
    };

    // MODE 1: B chunk fp32 load + fold gate*invq (chunk kc == head kc)
    float fpx[4];           // invq per handled pixel (fixed per thread)
    float4 breg[4];
    auto ldB = [&](int kc) {
#pragma unroll
        for (int j = 0; j < 4; j++) {
            int idx = tid + j * 256;
            int r = idx >> 3, c4 = idx & 7;
            int p = nbase + r;
            float f = fpx[j] * d_gate[(size_t)(b * 8 + kc) * HW + p];
            float4 v = *(const float4*)&d_qkvT[((size_t)b * HW + p) * 1024 + kc * 32 + c4 * 4];
            v.x *= f; v.y *= f; v.z *= f; v.w *= f;
            breg[j] = v;
        }
    };
    auto stB = [&](int s) {
#pragma unroll
        for (int j = 0; j < 4; j++) {
            int idx = tid + j * 256;
            int r = idx >> 3, c4 = idx & 7;
            float4 v = breg[j];
            __nv_bfloat16 hx = __float2bfloat16(v.x), hy = __float2bfloat16(v.y);
            __nv_bfloat16 hz = __float2bfloat16(v.z), hw = __float2bfloat16(v.w);
            __nv_bfloat162 h0; h0.x = hx; h0.y = hy;
            __nv_bfloat162 h1; h1.x = hz; h1.y = hw;
            __nv_bfloat162 l0, l1;
            l0.x = __float2bfloat16(v.x - __bfloat162float(hx));
            l0.y = __float2bfloat16(v.y - __bfloat162float(hy));
            l1.x = __float2bfloat16(v.z - __bfloat162float(hz));
            l1.y = __float2bfloat16(v.w - __bfloat162float(hw));
            char* ph = smem + SM_TILE(s, 2) + r * PITCH + c4 * 8;
            char* pl = smem + SM_TILE(s, 3) + r * PITCH + c4 * 8;
            *(__nv_bfloat162*)(ph) = h0; *(__nv_bfloat162*)(ph + 4) = h1;
            *(__nv_bfloat162*)(pl) = l0; *(__nv_bfloat162*)(pl + 4) = l1;
        }
    };

    float acc[4][4][4] = {};
    const int a_row = lane & 15;
    const int a_colh = (lane >> 4) << 3;
    const int b_row = (lane & 7) + ((lane >> 4) << 3);
    const int b_colh = ((lane >> 3) & 1) << 3;

    if (MODE == 0) {
        load4(0, 0); load4(1, 1);
    } else {
#pragma unroll
        for (int j = 0; j < 4; j++)
            fpx[j] = d_invq[b * HW + nbase + ((tid + j * 256) >> 3)];
        loadA(0, 0); loadA(1, 1);
        ldB(0); stB(0);
        ldB(1); stB(1);
        ldB(2);
    }

#pragma unroll
    for (int i = 0; i < 8; i++) {
        const int s = i % 3;
        if (i < 7) asm volatile("cp.async.wait_group 1;" ::: "memory");
        else       asm volatile("cp.async.wait_group 0;" ::: "memory");
        __syncthreads();
        if (i + 2 < 8) {
            const int sn = (i + 2) % 3;
            if (MODE == 0) {
                load4(i + 2, sn);
            } else {
                loadA(i + 2, sn);
                stB(sn);
                if (i + 3 < 8) ldB(i + 3);
            }
        }

        const uint32_t tAh = sb + SM_TILE(s, 0), tAl = sb + SM_TILE(s, 1);
        const uint32_t tBh = sb + SM_TILE(s, 2), tBl = sb + SM_TILE(s, 3);
#pragma unroll
        for (int ks = 0; ks < 2; ks++) {
            const int kh = ks * 16;
            uint32_t aH[4][4], aL[4][4], bH[4][2], bL[4][2];
#pragma unroll
            for (int mt = 0; mt < 4; mt++) {
                uint32_t off = (uint32_t)(m0w + mt * 16 + a_row) * PITCH + (kh + a_colh) * 2;
                ldsm4(aH[mt], tAh + off);
                ldsm4(aL[mt], tAl + off);
            }
#pragma unroll
            for (int bt = 0; bt < 2; bt++) {
                uint32_t off = (uint32_t)(n0w + bt * 16 + b_row) * PITCH + (kh + b_colh) * 2;
                uint32_t rh[4], rl[4];
                ldsm4(rh, tBh + off);
                ldsm4(rl, tBl + off);
                bH[bt * 2][0] = rh[0]; bH[bt * 2][1] = rh[1];
                bH[bt * 2 + 1][0] = rh[2]; bH[bt * 2 + 1][1] = rh[3];
                bL[bt * 2][0] = rl[0]; bL[bt * 2][1] = rl[1];
                bL[bt * 2 + 1][0] = rl[2]; bL[bt * 2 + 1][1] = rl[3];
            }
#pragma unroll
            for (int mt = 0; mt < 4; mt++)
#pragma unroll
                for (int nt = 0; nt < 4; nt++) {
                    mma16816(acc[mt][nt], aH[mt], bH[nt][0], bH[nt][1]);
                    mma16816(acc[mt][nt], aH[mt], bL[nt][0], bL[nt][1]);
                    mma16816(acc[mt][nt], aL[mt], bH[nt][0], bH[nt][1]);
                }
        }
    }

    if (MODE == 0) {
        // transposed epilogue via smem: sT[px][ch] (pitch 132 floats)
        float* sT = (float*)smem;
        __syncthreads();
#pragma unroll
        for (int mt = 0; mt < 4; mt++) {
            int rr0 = m0w + mt * 16 + (lane >> 2);
            int rr1 = rr0 + 8;
            float b0 = d_ball[mbase + rr0], b1 = d_ball[mbase + rr1];
#pragma unroll
            for (int nt = 0; nt < 4; nt++) {
                int cc = n0w + nt * 8 + (lane & 3) * 2;
                sT[(cc) * 132 + rr0]     = acc[mt][nt][0] + b0;
                sT[(cc + 1) * 132 + rr0] = acc[mt][nt][1] + b0;
                sT[(cc) * 132 + rr1]     = acc[mt][nt][2] + b1;
                sT[(cc + 1) * 132 + rr1] = acc[mt][nt][3] + b1;
            }
        }
        __syncthreads();
#pragma unroll
        for (int j = 0; j < 16; j++) {
            int idx = tid + j * 256;
            int px = idx >> 5, c4 = idx & 31;
            float4 v = *(float4*)&sT[px * 132 + c4 * 4];
            *(float4*)&d_qkvT[((size_t)b * HW + nbase + px) * 1024 + mbase + c4 * 4] = v;
        }
        if (mbase < 512 && tid < 128) {
            int px = tid;
            float s = 0.f;
#pragma unroll
            for (int c4 = 0; c4 < 32; c4++) {
                float4 v = *(float4*)&sT[px * 132 + c4 * 4];
                s += v.x * v.x + v.y * v.y + v.z * v.z + v.w * v.w;
            }
            d_ssqp[(size_t)(mbase >> 7) * (B_ * HW) + b * HW + nbase + px] = s;
        }
    } else {
        float* Cg = CoutExt + (size_t)b * 256 * HW;
#pragma unroll
        for (int mt = 0; mt < 4; mt++) {
            int r0 = mbase + m0w + mt * 16 + (lane >> 2);
            int r1 = r0 + 8;
            float sc0 = d_s[r0], t0 = d_t[r0], sc1 = d_s[r1], t1 = d_t[r1];
#pragma unroll
            for (int nt = 0; nt < 4; nt++) {
                int c = nbase + n0w + nt * 8 + (lane & 3) * 2;
                float2 o0, o1;
                o0.x = fmaxf(acc[mt][nt][0] * sc0 + t0, 0.f);
                o0.y = fmaxf(acc[mt][nt][1] * sc0 + t0, 0.f);
                o1.x = fmaxf(acc[mt][nt][2] * sc1 + t1, 0.f);
                o1.y = fmaxf(acc[mt][nt][3] * sc1 + t1, 0.f);
                *(float2*)&Cg[(size_t)r0 * HW + c] = o0;
                *(float2*)&Cg[(size_t)r1 * HW + c] = o1;
            }
        }
    }
}

// ---------------- K2s: finish pixelnorm factors --------------------------------
__global__ void k2s() {
    int i = blockIdx.x * blockDim.x + threadIdx.x;
    float sq = d_ssqp[i] + d_ssqp[B_ * HW + i];
    float sk = d_ssqp[2 * B_ * HW + i] + d_ssqp[3 * B_ * HW + i];
    d_invq[i] = rsqrtf(sq * (1.f / 256.f) + 1e-8f);
    d_invk[i] = rsqrtf(sk * (1.f / 256.f) + 1e-8f);
}

// ---------------- K3a: per-head partial kv = (k*invk) @ v^T (pixel-major) ------
__global__ __launch_bounds__(256) void k3a_kv() {
    int head = blockIdx.y, split = blockIdx.x;
    int b = head >> 3, h = head & 7;

    __shared__ float ks[128][32];
    __shared__ float vs[128][64];

    int tid = threadIdx.x;
    int tx = tid & 15, ty = tid >> 4;
    float acc[2][4] = {};

    for (int it = 0; it < 4; it++) {
        int pb = split * 512 + it * 128;
#pragma unroll
        for (int j = 0; j < 4; j++) {
            int idx = tid + j * 256;
            int r = idx >> 3, c4 = idx & 7;
            int p = pb + r;
            float iv = d_invk[b * HW + p];
            float4 v = *(const float4*)&d_qkvT[((size_t)b * HW + p) * 1024 + 256 + h * 32 + c4 * 4];
            v.x *= iv; v.y *= iv; v.z *= iv; v.w *= iv;
            *(float4*)&ks[r][c4 * 4] = v;
        }
#pragma unroll
        for (int j = 0; j < 8; j++) {
            int idx = tid + j * 256;
            int r = idx >> 4, c4 = idx & 15;
            int p = pb + r;
            float4 v = *(const float4*)&d_qkvT[((size_t)b * HW + p) * 1024 + 512 + h * 64 + c4 * 4];
            *(float4*)&vs[r][c4 * 4] = v;
        }
        __syncthreads();
#pragma unroll 4
        for (int p = 0; p < 128; p++) {
            float4 v4 = *(const float4*)&vs[p][tx * 4];
            float k0 = ks[p][ty * 2], k1 = ks[p][ty * 2 + 1];
            acc[0][0] += k0 * v4.x; acc[0][1] += k0 * v4.y;
            acc[0][2] += k0 * v4.z; acc[0][3] += k0 * v4.w;
            acc[1][0] += k1 * v4.x; acc[1][1] += k1 * v4.y;
            acc[1][2] += k1 * v4.z; acc[1][3] += k1 * v4.w;
        }
        __syncthreads();
    }
    float* out = d_kvpart + ((size_t)head * 8 + split) * 2048;
#pragma unroll
    for (int i = 0; i < 2; i++)
#pragma unroll
        for (int j = 0; j < 4; j++)
            out[(ty * 2 + i) * 64 + tx * 4 + j] = acc[i][j];
}

// ---------------- K3b: reduce kv, pixelnorm, m, Wf2 (writes bf16 hi/lo) --------
__global__ __launch_bounds__(256) void k3b_kvnorm(const float* __restrict__ Wf) {
    int head = blockIdx.x;
    int b = head >> 3, h = head & 7;
    __shared__ float skv[2048];
    __shared__ float nrm[64];
    int tid = threadIdx.x;
#pragma unroll
    for (int s = 0; s < 8; s++) {
        int idx = tid + s * 256;
        float sum = 0.f;
#pragma unroll
        for (int sp = 0; sp < 8; sp++)
            sum += d_kvpart[(size_t)(head * 8 + sp) * 2048 + idx];
        skv[idx] = sum;
    }
    __syncthreads();
    if (tid < 64) {
        float s = 0.f;
#pragma unroll
        for (int c = 0; c < 32; c++) { float v = skv[c * 64 + tid]; s += v * v; }
        nrm[tid] = rsqrtf(s * (1.f / 32.f) + 1e-8f);
    }
    __syncthreads();
#pragma unroll
    for (int s = 0; s < 8; s++) {
        int idx = tid + s * 256;
        skv[idx] *= nrm[idx & 63];
    }
    __syncthreads();
    if (tid < 32) {
        float s = 0.f;
#pragma unroll
        for (int C = 32; C < 64; C++) s += skv[tid * 64 + C];
        d_m[head * 32 + tid] = s * (1.f / 32.f);
    }
    // Wf2 row for output channel o = tid, columns h*32..h*32+31, write hi/lo bf16
    int o = tid;
    float wf[32];
#pragma unroll
    for (int c2 = 0; c2 < 32; c2++) wf[c2] = Wf[o * 256 + h * 32 + c2];
    size_t ob = (size_t)b * 65536 + o * 256 + h * 32;
    for (int c = 0; c < 32; c++) {
        float s = 0.f;
#pragma unroll
        for (int c2 = 0; c2 < 32; c2++) s += wf[c2] * skv[c * 64 + c2];
        __nv_bfloat16 hh = __float2bfloat16(s);
        d_W2_h[ob + c] = hh;
        d_W2_l[ob + c] = __float2bfloat16(s - __bfloat162float(hh));
    }
}

// ---------------- K4: spatial softmax gate (1024 threads) ----------------------
__global__ __launch_bounds__(1024) void k4_gate() {
    int head = blockIdx.x;
    int b = head >> 3, h = head & 7;
    __shared__ float4 m4[8];
    __shared__ float red[1024];
    int tid = threadIdx.x;
    if (tid < 8) m4[tid] = *(const float4*)&d_m[head * 32 + tid * 4];
    __syncthreads();

    float z[4];
    float lmax = -1e30f;
#pragma unroll
    for (int i = 0; i < 4; i++) {
        int p = tid + i * 1024;
        const float4* row = (const float4*)&d_qkvT[((size_t)b * HW + p) * 1024 + h * 32];
        float s = 0.f;
#pragma unroll
        for (int c4 = 0; c4 < 8; c4++) {
            float4 q = row[c4], m = m4[c4];
            s += q.x * m.x + q.y * m.y + q.z * m.z + q.w * m.w;
        }
        z[i] = s * d_invq[b * HW + p] * (1.f / 64.f);
        lmax = fmaxf(lmax, z[i]);
    }
    red[tid] = lmax; __syncthreads();
    for (int st = 512; st > 0; st >>= 1) {
        if (tid < st) red[tid] = fmaxf(red[tid], red[tid + st]);
        __syncthreads();
    }
    float gmax = red[0]; __syncthreads();
    float lsum = 0.f;
#pragma unroll
    for (int i = 0; i < 4; i++) { z[i] = __expf(z[i] - gmax); lsum += z[i]; }
    red[tid] = lsum; __syncthreads();
    for (int st = 512; st > 0; st >>= 1) {
        if (tid < st) red[tid] += red[tid + st];
        __syncthreads();
    }
    float inv = 1.f / red[0];
#pragma unroll
    for (int i = 0; i < 4; i++)
        d_gate[(size_t)head * HW + tid + i * 1024] = z[i] * inv;
}

// ---------------- launch --------------------------------------------------------
extern "C" void kernel_launch(void* const* d_in, const int* in_sizes, int n_in,
                              void* d_out, int out_size) {
    const float* x     = (const float*)d_in[0];
    const float* Wq    = (const float*)d_in[1];
    const float* bq    = (const float*)d_in[2];
    const float* Wk    = (const float*)d_in[3];
    const float* bk    = (const float*)d_in[4];
    const float* Wv    = (const float*)d_in[5];
    const float* bv    = (const float*)d_in[6];
    const float* Wf    = (const float*)d_in[7];
    const float* bf    = (const float*)d_in[8];
    const float* gamma = (const float*)d_in[9];
    const float* beta  = (const float*)d_in[10];
    const float* mean  = (const float*)d_in[11];
    const float* var   = (const float*)d_in[12];
    float* out = (float*)d_out;

    static bool attr_set = false;
    if (!attr_set) {
        cudaFuncSetAttribute(k_mma<0>, cudaFuncAttributeMaxDynamicSharedMemorySize, SMEM_SZ);
        cudaFuncSetAttribute(k_mma<1>, cudaFuncAttributeMaxDynamicSharedMemorySize, SMEM_SZ);
        attr_set = true;
    }

    k0_prep<<<(1024 * 256 + 255) / 256, 256>>>(Wq, bq, Wk, bk, Wv, bv, bf, gamma, beta, mean, var);
    k_convx<<<dim3(128, 4, B_), 256>>>(x);
    k_mma<0><<<dim3(32, 8, B_), 256, SMEM_SZ>>>(nullptr);
    k2s<<<256, 128>>>();
    k3a_kv<<<dim3(8, 64), 256>>>();
    k3b_kvnorm<<<64, 256>>>(Wf);
    k4_gate<<<64, 1024>>>();
    k_mma<1><<<dim3(32, 2, B_), 256, SMEM_SZ>>>(out);
}

// round 6
// speedup vs baseline: 1.1531x; 1.1531x over previous
#include <cuda_runtime.h>
#include <cuda_fp16.h>
#include <cstdint>

#define HW 4096
#define B_ 8

// ---------------- scratch -----------------------------------------------------
__device__ float d_qkvT[(size_t)B_ * HW * 1024];   // pixel-major: [b][p][ch] q0-255,k256-511,v512-1023
__device__ float d_ssqp[4 * B_ * HW];              // partial ssq tiles q0,q1,k0,k1
__device__ float d_invq[B_ * HW];
__device__ float d_invk[B_ * HW];
__device__ float d_kvpart[64 * 8 * 2048];
__device__ float d_m[64 * 32];
__device__ float d_gate[64 * HW];
__device__ float d_ball[1024];
__device__ float d_s[256];
__device__ float d_t[256];
__device__ __half d_Wq_h[1024 * 256], d_Wq_l[1024 * 256];
__device__ __half d_xT_h[(size_t)B_ * HW * 256];
__device__ __half d_W2_h[B_ * 256 * 256], d_W2_l[B_ * 256 * 256];

// ---------------- helpers (sm_80-baseline PTX only) ----------------------------
__device__ __forceinline__ uint32_t smem_u32(const void* p) {
    uint32_t a;
    asm("{ .reg .u64 t; cvta.to.shared.u64 t, %1; cvt.u32.u64 %0, t; }" : "=r"(a) : "l"(p));
    return a;
}
__device__ __forceinline__ void cp16(uint32_t dst, const void* src) {
    asm volatile("cp.async.cg.shared.global [%0], [%1], 16;" :: "r"(dst), "l"(src));
}
#define CP_COMMIT() asm volatile("cp.async.commit_group;" ::: "memory")

__device__ __forceinline__ void ldsm4(uint32_t* r, uint32_t addr) {
    asm volatile("ldmatrix.sync.aligned.m8n8.x4.shared.b16 {%0,%1,%2,%3}, [%4];"
        : "=r"(r[0]), "=r"(r[1]), "=r"(r[2]), "=r"(r[3]) : "r"(addr));
}
__device__ __forceinline__ void mma16816(float* d, const uint32_t* a, uint32_t b0, uint32_t b1) {
    asm volatile("mma.sync.aligned.m16n8k16.row.col.f32.f16.f16.f32 "
        "{%0,%1,%2,%3}, {%4,%5,%6,%7}, {%8,%9}, {%0,%1,%2,%3};"
        : "+f"(d[0]), "+f"(d[1]), "+f"(d[2]), "+f"(d[3])
        : "r"(a[0]), "r"(a[1]), "r"(a[2]), "r"(a[3]), "r"(b0), "r"(b1));
}

// ---------------- K0: pack weights hi/lo, biases, BN fold ----------------------
__global__ void k0_prep(const float* __restrict__ Wq, const float* __restrict__ bq,
                        const float* __restrict__ Wk, const float* __restrict__ bk,
                        const float* __restrict__ Wv, const float* __restrict__ bv,
                        const float* __restrict__ bf,
                        const float* __restrict__ gamma, const float* __restrict__ beta,
                        const float* __restrict__ mean,  const float* __restrict__ var) {
    int idx = blockIdx.x * blockDim.x + threadIdx.x;
    if (idx < 1024 * 256) {
        int r = idx >> 8, c = idx & 255;
        float w = (r < 256) ? Wq[r * 256 + c] : (r < 512) ? Wk[(r - 256) * 256 + c] : Wv[(r - 512) * 256 + c];
        __half h = __float2half(w);
        d_Wq_h[idx] = h;
        d_Wq_l[idx] = __float2half(w - __half2float(h));
    }
    if (idx < 1024)
        d_ball[idx] = (idx < 256) ? bq[idx] : (idx < 512) ? bk[idx - 256] : bv[idx - 512];
    if (idx < 256) {
        float s = gamma[idx] * rsqrtf(var[idx] + 1e-5f);
        d_s[idx] = s;
        d_t[idx] = (bf[idx] - mean[idx]) * s + beta[idx];
    }
}

// ---------------- convert x -> xT fp16 (transpose) -----------------------------
__global__ __launch_bounds__(256) void k_convx(const float* __restrict__ x) {
    __shared__ float t[64][33];
    int p0 = blockIdx.x * 32, c0 = blockIdx.y * 64, b = blockIdx.z;
    const float* src = x + ((size_t)b * 256 + c0) * HW + p0;
    int tid = threadIdx.x;
#pragma unroll
    for (int j = 0; j < 8; j++) {
        int idx = tid + j * 256;
        int cc = idx >> 5, pp = idx & 31;
        t[cc][pp] = src[(size_t)cc * HW + pp];
    }
    __syncthreads();
    __half2* oh = (__half2*)d_xT_h;
#pragma unroll
    for (int j = 0; j < 4; j++) {
        int idx = tid + j * 256;
        int p = idx >> 5, pr = idx & 31;
        __half2 hh;
        hh.x = __float2half(t[pr * 2][p]);
        hh.y = __float2half(t[pr * 2 + 1][p]);
        oh[((size_t)b * HW + p0 + p) * 128 + (c0 >> 1) + pr] = hh;
    }
}

// ---------------- mma.sync GEMM (fp16, 2-term: AhBh + AlBh) --------------------
// MODE 0: qkv = Wqkv @ x^T  -> writes d_qkvT transposed + partial ssq
// MODE 1: out = Wf2 @ z^T   -> B operand (z = gate*invq*q) folded in loader
// Block 128x128, 8 warps (2x4), warp tile 64x32, K-chunk 32, 2-stage cp.async.
#define PITCH 80
#define TILE_BYTES (128 * PITCH)
#define SM_TILE(s, t) (((s) * 3 + (t)) * TILE_BYTES)
#define SMEM_SZ 69632

template <int MODE>
__global__ __launch_bounds__(256, 1) void k_mma(float* __restrict__ CoutExt) {
    extern __shared__ char smem[];
    uint32_t sb = smem_u32(smem);
    const int tid = threadIdx.x;
    const int lane = tid & 31;
    const int wid = tid >> 5;
    const int wm = wid >> 2, wn = wid & 3;
    const int m0w = wm * 64, n0w = wn * 32;
    const int b = blockIdx.z;
    const int nbase = blockIdx.x * 128;
    const int mbase = blockIdx.y * 128;

    const __half* Ah = (MODE == 0) ? d_Wq_h + (size_t)mbase * 256
                                   : d_W2_h + (size_t)b * 65536 + (size_t)mbase * 256;
    const __half* Al = (MODE == 0) ? d_Wq_l + (size_t)mbase * 256
                                   : d_W2_l + (size_t)b * 65536 + (size_t)mbase * 256;
    const __half* Bh = d_xT_h + (size_t)b * HW * 256 + (size_t)nbase * 256;

    const __half* bases3[3] = {Ah, Al, Bh};
    const __half* bases2[2] = {Ah, Al};

    // MODE 0: 3 tiles x 128 rows x 4 chunks(16B) = 1536 / 256 thr = 6 each
    auto load3 = [&](int kc, int s) {
#pragma unroll
        for (int j = 0; j < 6; j++) {
            int g = tid + j * 256;
            int t = g >> 9, w = g & 511;
            int r = w >> 2, c = w & 3;
            const char* src = (const char*)bases3[t] + ((size_t)r * 256 + kc * 32 + c * 8) * 2;
            cp16(sb + SM_TILE(s, t) + r * PITCH + c * 16, src);
        }
        CP_COMMIT();
    };
    // MODE 1: A tiles only
    auto loadA = [&](int kc, int s) {
#pragma unroll
        for (int j = 0; j < 4; j++) {
            int g = tid + j * 256;
            int t = g >> 9, w = g & 511;
            int r = w >> 2, c = w & 3;
            const char* src = (const char*)bases2[t] + ((size_t)r * 256 + kc * 32 + c * 8) * 2;
            cp16(sb + SM_TILE(s, t) + r * PITCH + c * 16, src);
        }
        CP_COMMIT();
    };

    // MODE 1: B chunk fp32 load + fold gate*invq (chunk kc == head kc)
    float fpx[4];
    float4 breg[4];
    auto ldB = [&](int kc) {
#pragma unroll
        for (int j = 0; j < 4; j++) {
            int idx = tid + j * 256;
            int r = idx >> 3, c4 = idx & 7;
            int p = nbase + r;
            float f = fpx[j] * d_gate[(size_t)(b * 8 + kc) * HW + p];
            float4 v = *(const float4*)&d_qkvT[((size_t)b * HW + p) * 1024 + kc * 32 + c4 * 4];
            v.x *= f; v.y *= f; v.z *= f; v.w *= f;
            breg[j] = v;
        }
    };
    auto stB = [&](int s) {
#pragma unroll
        for (int j = 0; j < 4; j++) {
            int idx = tid + j * 256;
            int r = idx >> 3, c4 = idx & 7;
            float4 v = breg[j];
            __half2 h0, h1;
            h0.x = __float2half(v.x); h0.y = __float2half(v.y);
            h1.x = __float2half(v.z); h1.y = __float2half(v.w);
            char* ph = smem + SM_TILE(s, 2) + r * PITCH + c4 * 8;
            *(__half2*)(ph) = h0; *(__half2*)(ph + 4) = h1;
        }
    };

    float acc[4][4][4] = {};
    const int a_row = lane & 15;
    const int a_colh = (lane >> 4) << 3;
    const int b_row = (lane & 7) + ((lane >> 4) << 3);
    const int b_colh = ((lane >> 3) & 1) << 3;

    if (MODE == 0) {
        load3(0, 0); load3(1, 1);
    } else {
#pragma unroll
        for (int j = 0; j < 4; j++)
            fpx[j] = d_invq[b * HW + nbase + ((tid + j * 256) >> 3)];
        loadA(0, 0); loadA(1, 1);
        ldB(0);
    }

#pragma unroll
    for (int i = 0; i < 8; i++) {
        const int s = i & 1;
        if (MODE == 1) stB(s);
        if (i < 6) asm volatile("cp.async.wait_group 1;" ::: "memory");
        else       asm volatile("cp.async.wait_group 0;" ::: "memory");
        __syncthreads();
        if (MODE == 1 && i + 1 < 8) ldB(i + 1);

        const uint32_t tAh = sb + SM_TILE(s, 0), tAl = sb + SM_TILE(s, 1);
        const uint32_t tBh = sb + SM_TILE(s, 2);
#pragma unroll
        for (int ks = 0; ks < 2; ks++) {
            const int kh = ks * 16;
            uint32_t aH[4][4], aL[4][4], bH[4][2];
#pragma unroll
            for (int mt = 0; mt < 4; mt++) {
                uint32_t off = (uint32_t)(m0w + mt * 16 + a_row) * PITCH + (kh + a_colh) * 2;
                ldsm4(aH[mt], tAh + off);
                ldsm4(aL[mt], tAl + off);
            }
#pragma unroll
            for (int bt = 0; bt < 2; bt++) {
                uint32_t off = (uint32_t)(n0w + bt * 16 + b_row) * PITCH + (kh + b_colh) * 2;
                uint32_t rh[4];
                ldsm4(rh, tBh + off);
                bH[bt * 2][0] = rh[0]; bH[bt * 2][1] = rh[1];
                bH[bt * 2 + 1][0] = rh[2]; bH[bt * 2 + 1][1] = rh[3];
            }
#pragma unroll
            for (int mt = 0; mt < 4; mt++)
#pragma unroll
                for (int nt = 0; nt < 4; nt++) {
                    mma16816(acc[mt][nt], aH[mt], bH[nt][0], bH[nt][1]);
                    mma16816(acc[mt][nt], aL[mt], bH[nt][0], bH[nt][1]);
                }
        }
        __syncthreads();
        if (i + 2 < 8) { if (MODE == 0) load3(i + 2, s); else loadA(i + 2, s); }
    }

    if (MODE == 0) {
        // transposed epilogue via smem: sT[px][ch] (pitch 132 floats)
        float* sT = (float*)smem;
        __syncthreads();
#pragma unroll
        for (int mt = 0; mt < 4; mt++) {
            int rr0 = m0w + mt * 16 + (lane >> 2);
            int rr1 = rr0 + 8;
            float b0 = d_ball[mbase + rr0], b1 = d_ball[mbase + rr1];
#pragma unroll
            for (int nt = 0; nt < 4; nt++) {
                int cc = n0w + nt * 8 + (lane & 3) * 2;
                sT[(cc) * 132 + rr0]     = acc[mt][nt][0] + b0;
                sT[(cc + 1) * 132 + rr0] = acc[mt][nt][1] + b0;
                sT[(cc) * 132 + rr1]     = acc[mt][nt][2] + b1;
                sT[(cc + 1) * 132 + rr1] = acc[mt][nt][3] + b1;
            }
        }
        __syncthreads();
#pragma unroll
        for (int j = 0; j < 16; j++) {
            int idx = tid + j * 256;
            int px = idx >> 5, c4 = idx & 31;
            float4 v = *(float4*)&sT[px * 132 + c4 * 4];
            *(float4*)&d_qkvT[((size_t)b * HW + nbase + px) * 1024 + mbase + c4 * 4] = v;
        }
        if (mbase < 512 && tid < 128) {
            int px = tid;
            float s = 0.f;
#pragma unroll
            for (int c4 = 0; c4 < 32; c4++) {
                float4 v = *(float4*)&sT[px * 132 + c4 * 4];
                s += v.x * v.x + v.y * v.y + v.z * v.z + v.w * v.w;
            }
            d_ssqp[(size_t)(mbase >> 7) * (B_ * HW) + b * HW + nbase + px] = s;
        }
    } else {
        float* Cg = CoutExt + (size_t)b * 256 * HW;
#pragma unroll
        for (int mt = 0; mt < 4; mt++) {
            int r0 = mbase + m0w + mt * 16 + (lane >> 2);
            int r1 = r0 + 8;
            float sc0 = d_s[r0], t0 = d_t[r0], sc1 = d_s[r1], t1 = d_t[r1];
#pragma unroll
            for (int nt = 0; nt < 4; nt++) {
                int c = nbase + n0w + nt * 8 + (lane & 3) * 2;
                float2 o0, o1;
                o0.x = fmaxf(acc[mt][nt][0] * sc0 + t0, 0.f);
                o0.y = fmaxf(acc[mt][nt][1] * sc0 + t0, 0.f);
                o1.x = fmaxf(acc[mt][nt][2] * sc1 + t1, 0.f);
                o1.y = fmaxf(acc[mt][nt][3] * sc1 + t1, 0.f);
                *(float2*)&Cg[(size_t)r0 * HW + c] = o0;
                *(float2*)&Cg[(size_t)r1 * HW + c] = o1;
            }
        }
    }
}

// ---------------- K2s: finish pixelnorm factors --------------------------------
__global__ void k2s() {
    int i = blockIdx.x * blockDim.x + threadIdx.x;
    float sq = d_ssqp[i] + d_ssqp[B_ * HW + i];
    float sk = d_ssqp[2 * B_ * HW + i] + d_ssqp[3 * B_ * HW + i];
    d_invq[i] = rsqrtf(sq * (1.f / 256.f) + 1e-8f);
    d_invk[i] = rsqrtf(sk * (1.f / 256.f) + 1e-8f);
}

// ---------------- K3a: per-head partial kv = (k*invk) @ v^T (pixel-major) ------
__global__ __launch_bounds__(256) void k3a_kv() {
    int head = blockIdx.y, split = blockIdx.x;
    int b = head >> 3, h = head & 7;

    __shared__ float ks[128][32];
    __shared__ float vs[128][64];

    int tid = threadIdx.x;
    int tx = tid & 15, ty = tid >> 4;
    float acc[2][4] = {};

    for (int it = 0; it < 4; it++) {
        int pb = split * 512 + it * 128;
#pragma unroll
        for (int j = 0; j < 4; j++) {
            int idx = tid + j * 256;
            int r = idx >> 3, c4 = idx & 7;
            int p = pb + r;
            float iv = d_invk[b * HW + p];
            float4 v = *(const float4*)&d_qkvT[((size_t)b * HW + p) * 1024 + 256 + h * 32 + c4 * 4];
            v.x *= iv; v.y *= iv; v.z *= iv; v.w *= iv;
            *(float4*)&ks[r][c4 * 4] = v;
        }
#pragma unroll
        for (int j = 0; j < 8; j++) {
            int idx = tid + j * 256;
            int r = idx >> 4, c4 = idx & 15;
            int p = pb + r;
            float4 v = *(const float4*)&d_qkvT[((size_t)b * HW + p) * 1024 + 512 + h * 64 + c4 * 4];
            *(float4*)&vs[r][c4 * 4] = v;
        }
        __syncthreads();
#pragma unroll 4
        for (int p = 0; p < 128; p++) {
            float4 v4 = *(const float4*)&vs[p][tx * 4];
            float k0 = ks[p][ty * 2], k1 = ks[p][ty * 2 + 1];
            acc[0][0] += k0 * v4.x; acc[0][1] += k0 * v4.y;
            acc[0][2] += k0 * v4.z; acc[0][3] += k0 * v4.w;
            acc[1][0] += k1 * v4.x; acc[1][1] += k1 * v4.y;
            acc[1][2] += k1 * v4.z; acc[1][3] += k1 * v4.w;
        }
        __syncthreads();
    }
    float* out = d_kvpart + ((size_t)head * 8 + split) * 2048;
#pragma unroll
    for (int i = 0; i < 2; i++)
#pragma unroll
        for (int j = 0; j < 4; j++)
            out[(ty * 2 + i) * 64 + tx * 4 + j] = acc[i][j];
}

// ---------------- K3b: reduce kv, pixelnorm, m, Wf2 (writes fp16 hi/lo) --------
__global__ __launch_bounds__(256) void k3b_kvnorm(const float* __restrict__ Wf) {
    int head = blockIdx.x;
    int b = head >> 3, h = head & 7;
    __shared__ float skv[2048];
    __shared__ float nrm[64];
    int tid = threadIdx.x;
#pragma unroll
    for (int s = 0; s < 8; s++) {
        int idx = tid + s * 256;
        float sum = 0.f;
#pragma unroll
        for (int sp = 0; sp < 8; sp++)
            sum += d_kvpart[(size_t)(head * 8 + sp) * 2048 + idx];
        skv[idx] = sum;
    }
    __syncthreads();
    if (tid < 64) {
        float s = 0.f;
#pragma unroll
        for (int c = 0; c < 32; c++) { float v = skv[c * 64 + tid]; s += v * v; }
        nrm[tid] = rsqrtf(s * (1.f / 32.f) + 1e-8f);
    }
    __syncthreads();
#pragma unroll
    for (int s = 0; s < 8; s++) {
        int idx = tid + s * 256;
        skv[idx] *= nrm[idx & 63];
    }
    __syncthreads();
    if (tid < 32) {
        float s = 0.f;
#pragma unroll
        for (int C = 32; C < 64; C++) s += skv[tid * 64 + C];
        d_m[head * 32 + tid] = s * (1.f / 32.f);
    }
    int o = tid;
    float wf[32];
#pragma unroll
    for (int c2 = 0; c2 < 32; c2++) wf[c2] = Wf[o * 256 + h * 32 + c2];
    size_t ob = (size_t)b * 65536 + o * 256 + h * 32;
    for (int c = 0; c < 32; c++) {
        float s = 0.f;
#pragma unroll
        for (int c2 = 0; c2 < 32; c2++) s += wf[c2] * skv[c * 64 + c2];
        __half hh = __float2half(s);
        d_W2_h[ob + c] = hh;
        d_W2_l[ob + c] = __float2half(s - __half2float(hh));
    }
}

// ---------------- K4: spatial softmax gate (1024 threads) ----------------------
__global__ __launch_bounds__(1024) void k4_gate() {
    int head = blockIdx.x;
    int b = head >> 3, h = head & 7;
    __shared__ float4 m4[8];
    __shared__ float red[1024];
    int tid = threadIdx.x;
    if (tid < 8) m4[tid] = *(const float4*)&d_m[head * 32 + tid * 4];
    __syncthreads();

    float z[4];
    float lmax = -1e30f;
#pragma unroll
    for (int i = 0; i < 4; i++) {
        int p = tid + i * 1024;
        const float4* row = (const float4*)&d_qkvT[((size_t)b * HW + p) * 1024 + h * 32];
        float s = 0.f;
#pragma unroll
        for (int c4 = 0; c4 < 8; c4++) {
            float4 q = row[c4], m = m4[c4];
            s += q.x * m.x + q.y * m.y + q.z * m.z + q.w * m.w;
        }
        z[i] = s * d_invq[b * HW + p] * (1.f / 64.f);
        lmax = fmaxf(lmax, z[i]);
    }
    red[tid] = lmax; __syncthreads();
    for (int st = 512; st > 0; st >>= 1) {
        if (tid < st) red[tid] = fmaxf(red[tid], red[tid + st]);
        __syncthreads();
    }
    float gmax = red[0]; __syncthreads();
    float lsum = 0.f;
#pragma unroll
    for (int i = 0; i < 4; i++) { z[i] = __expf(z[i] - gmax); lsum += z[i]; }
    red[tid] = lsum; __syncthreads();
    for (int st = 512; st > 0; st >>= 1) {
        if (tid < st) red[tid] += red[tid + st];
        __syncthreads();
    }
    float inv = 1.f / red[0];
#pragma unroll
    for (int i = 0; i < 4; i++)
        d_gate[(size_t)head * HW + tid + i * 1024] = z[i] * inv;
}

// ---------------- launch --------------------------------------------------------
extern "C" void kernel_launch(void* const* d_in, const int* in_sizes, int n_in,
                              void* d_out, int out_size) {
    const float* x     = (const float*)d_in[0];
    const float* Wq    = (const float*)d_in[1];
    const float* bq    = (const float*)d_in[2];
    const float* Wk    = (const float*)d_in[3];
    const float* bk    = (const float*)d_in[4];
    const float* Wv    = (const float*)d_in[5];
    const float* bv    = (const float*)d_in[6];
    const float* Wf    = (const float*)d_in[7];
    const float* bf    = (const float*)d_in[8];
    const float* gamma = (const float*)d_in[9];
    const float* beta  = (const float*)d_in[10];
    const float* mean  = (const float*)d_in[11];
    const float* var   = (const float*)d_in[12];
    float* out = (float*)d_out;

    static bool attr_set = false;
    if (!attr_set) {
        cudaFuncSetAttribute(k_mma<0>, cudaFuncAttributeMaxDynamicSharedMemorySize, SMEM_SZ);
        cudaFuncSetAttribute(k_mma<1>, cudaFuncAttributeMaxDynamicSharedMemorySize, SMEM_SZ);
        attr_set = true;
    }

    k0_prep<<<(1024 * 256 + 255) / 256, 256>>>(Wq, bq, Wk, bk, Wv, bv, bf, gamma, beta, mean, var);
    k_convx<<<dim3(128, 4, B_), 256>>>(x);
    k_mma<0><<<dim3(32, 8, B_), 256, SMEM_SZ>>>(nullptr);
    k2s<<<256, 128>>>();
    k3a_kv<<<dim3(8, 64), 256>>>();
    k3b_kvnorm<<<64, 256>>>(Wf);
    k4_gate<<<64, 1024>>>();
    k_mma<1><<<dim3(32, 2, B_), 256, SMEM_SZ>>>(out);
}

// round 7
// speedup vs baseline: 1.3292x; 1.1527x over previous
#include <cuda_runtime.h>
#include <cuda_fp16.h>
#include <cstdint>

#define HW 4096
#define B_ 8

// ---------------- scratch -----------------------------------------------------
__device__ __half d_qkvT[(size_t)B_ * HW * 1024];  // pixel-major fp16: [b][p][ch]
__device__ float d_ssqp[4 * B_ * HW];              // partial ssq tiles q0,q1,k0,k1
__device__ float d_invq[B_ * HW];
__device__ float d_invk[B_ * HW];
__device__ float d_kvpart[64 * 8 * 2048];
__device__ float d_m[64 * 32];
__device__ float d_gate[64 * HW];
__device__ float d_ball[1024];
__device__ float d_s[256];
__device__ float d_t[256];
__device__ __half d_Wq_h[1024 * 256];
__device__ __half d_xT_h[(size_t)B_ * HW * 256];
__device__ __half d_W2_h[B_ * 256 * 256];

// ---------------- helpers -------------------------------------------------------
__device__ __forceinline__ uint32_t smem_u32(const void* p) {
    uint32_t a;
    asm("{ .reg .u64 t; cvta.to.shared.u64 t, %1; cvt.u32.u64 %0, t; }" : "=r"(a) : "l"(p));
    return a;
}
__device__ __forceinline__ void cp16(uint32_t dst, const void* src) {
    asm volatile("cp.async.cg.shared.global [%0], [%1], 16;" :: "r"(dst), "l"(src));
}
#define CP_COMMIT() asm volatile("cp.async.commit_group;" ::: "memory")

__device__ __forceinline__ void ldsm4(uint32_t* r, uint32_t addr) {
    asm volatile("ldmatrix.sync.aligned.m8n8.x4.shared.b16 {%0,%1,%2,%3}, [%4];"
        : "=r"(r[0]), "=r"(r[1]), "=r"(r[2]), "=r"(r[3]) : "r"(addr));
}
__device__ __forceinline__ void mma16816(float* d, const uint32_t* a, uint32_t b0, uint32_t b1) {
    asm volatile("mma.sync.aligned.m16n8k16.row.col.f32.f16.f16.f32 "
        "{%0,%1,%2,%3}, {%4,%5,%6,%7}, {%8,%9}, {%0,%1,%2,%3};"
        : "+f"(d[0]), "+f"(d[1]), "+f"(d[2]), "+f"(d[3])
        : "r"(a[0]), "r"(a[1]), "r"(a[2]), "r"(a[3]), "r"(b0), "r"(b1));
}

// ---------------- K0: pack weights fp16, biases, BN fold -----------------------
__global__ void k0_prep(const float* __restrict__ Wq, const float* __restrict__ bq,
                        const float* __restrict__ Wk, const float* __restrict__ bk,
                        const float* __restrict__ Wv, const float* __restrict__ bv,
                        const float* __restrict__ bf,
                        const float* __restrict__ gamma, const float* __restrict__ beta,
                        const float* __restrict__ mean,  const float* __restrict__ var) {
    int idx = blockIdx.x * blockDim.x + threadIdx.x;
    if (idx < 1024 * 256) {
        int r = idx >> 8, c = idx & 255;
        float w = (r < 256) ? Wq[r * 256 + c] : (r < 512) ? Wk[(r - 256) * 256 + c] : Wv[(r - 512) * 256 + c];
        d_Wq_h[idx] = __float2half(w);
    }
    if (idx < 1024)
        d_ball[idx] = (idx < 256) ? bq[idx] : (idx < 512) ? bk[idx - 256] : bv[idx - 512];
    if (idx < 256) {
        float s = gamma[idx] * rsqrtf(var[idx] + 1e-5f);
        d_s[idx] = s;
        d_t[idx] = (bf[idx] - mean[idx]) * s + beta[idx];
    }
}

// ---------------- convert x -> xT fp16 (transpose) -----------------------------
__global__ __launch_bounds__(256) void k_convx(const float* __restrict__ x) {
    __shared__ float t[64][33];
    int p0 = blockIdx.x * 32, c0 = blockIdx.y * 64, b = blockIdx.z;
    const float* src = x + ((size_t)b * 256 + c0) * HW + p0;
    int tid = threadIdx.x;
#pragma unroll
    for (int j = 0; j < 8; j++) {
        int idx = tid + j * 256;
        int cc = idx >> 5, pp = idx & 31;
        t[cc][pp] = src[(size_t)cc * HW + pp];
    }
    __syncthreads();
    __half2* oh = (__half2*)d_xT_h;
#pragma unroll
    for (int j = 0; j < 4; j++) {
        int idx = tid + j * 256;
        int p = idx >> 5, pr = idx & 31;
        oh[((size_t)b * HW + p0 + p) * 128 + (c0 >> 1) + pr] =
            __floats2half2_rn(t[pr * 2][p], t[pr * 2 + 1][p]);
    }
}

// ---------------- mma.sync GEMM (fp16 single-term) -----------------------------
// MODE 0: qkv = Wqkv @ x^T  -> writes d_qkvT (fp16, transposed) + partial ssq
// MODE 1: out = Wf2 @ z^T   -> B operand (z = gate*invq*q) folded in loader
// Block 128x128, 8 warps (2x4), warp tile 64x32, K-chunk 32, 2-stage cp.async.
#define PITCH 80
#define TILE_BYTES (128 * PITCH)
#define SM_TILE(s, t) (((s) * 2 + (t)) * TILE_BYTES)
#define SMEM_SZ 69632

template <int MODE>
__global__ __launch_bounds__(256, 1) void k_mma(float* __restrict__ CoutExt) {
    extern __shared__ char smem[];
    uint32_t sb = smem_u32(smem);
    const int tid = threadIdx.x;
    const int lane = tid & 31;
    const int wid = tid >> 5;
    const int wm = wid >> 2, wn = wid & 3;
    const int m0w = wm * 64, n0w = wn * 32;
    const int b = blockIdx.z;
    const int nbase = blockIdx.x * 128;
    const int mbase = blockIdx.y * 128;

    const __half* Ah = (MODE == 0) ? d_Wq_h + (size_t)mbase * 256
                                   : d_W2_h + (size_t)b * 65536 + (size_t)mbase * 256;
    const __half* Bh = d_xT_h + (size_t)b * HW * 256 + (size_t)nbase * 256;

    const __half* bases2[2] = {Ah, Bh};

    // MODE 0: 2 tiles x 128 rows x 4 chunks(16B) = 1024 / 256 thr = 4 each
    auto load2 = [&](int kc, int s) {
#pragma unroll
        for (int j = 0; j < 4; j++) {
            int g = tid + j * 256;
            int t = g >> 9, w = g & 511;
            int r = w >> 2, c = w & 3;
            const char* src = (const char*)bases2[t] + ((size_t)r * 256 + kc * 32 + c * 8) * 2;
            cp16(sb + SM_TILE(s, t) + r * PITCH + c * 16, src);
        }
        CP_COMMIT();
    };
    // MODE 1: A tile only (512 chunks / 256 = 2 each)
    auto loadA = [&](int kc, int s) {
#pragma unroll
        for (int j = 0; j < 2; j++) {
            int g = tid + j * 256;
            int r = g >> 2, c = g & 3;
            const char* src = (const char*)Ah + ((size_t)r * 256 + kc * 32 + c * 8) * 2;
            cp16(sb + SM_TILE(s, 0) + r * PITCH + c * 16, src);
        }
        CP_COMMIT();
    };

    // MODE 1: B chunk fp16 load + fold gate*invq (chunk kc == head kc)
    float fpx[2];
    float breg[2][8];
    auto ldB = [&](int kc) {
#pragma unroll
        for (int j = 0; j < 2; j++) {
            int idx = tid + j * 256;              // 0..511
            int r = idx >> 2, c8 = idx & 3;       // px, group of 8 halves
            int p = nbase + r;
            float f = fpx[j] * d_gate[(size_t)(b * 8 + kc) * HW + p];
            const __half2* src = (const __half2*)&d_qkvT[((size_t)b * HW + p) * 1024 + kc * 32 + c8 * 8];
#pragma unroll
            for (int u = 0; u < 4; u++) {
                float2 v = __half22float2(src[u]);
                breg[j][u * 2]     = v.x * f;
                breg[j][u * 2 + 1] = v.y * f;
            }
        }
    };
    auto stB = [&](int s) {
#pragma unroll
        for (int j = 0; j < 2; j++) {
            int idx = tid + j * 256;
            int r = idx >> 2, c8 = idx & 3;
            __half2* dst = (__half2*)(smem + SM_TILE(s, 1) + r * PITCH + c8 * 16);
#pragma unroll
            for (int u = 0; u < 4; u++)
                dst[u] = __floats2half2_rn(breg[j][u * 2], breg[j][u * 2 + 1]);
        }
    };

    float acc[4][4][4] = {};
    const int a_row = lane & 15;
    const int a_colh = (lane >> 4) << 3;
    const int b_row = (lane & 7) + ((lane >> 4) << 3);
    const int b_colh = ((lane >> 3) & 1) << 3;

    if (MODE == 0) {
        load2(0, 0); load2(1, 1);
    } else {
#pragma unroll
        for (int j = 0; j < 2; j++)
            fpx[j] = d_invq[b * HW + nbase + ((tid + j * 256) >> 2)];
        loadA(0, 0); loadA(1, 1);
        ldB(0);
    }

#pragma unroll
    for (int i = 0; i < 8; i++) {
        const int s = i & 1;
        if (MODE == 1) stB(s);
        if (i < 6) asm volatile("cp.async.wait_group 1;" ::: "memory");
        else       asm volatile("cp.async.wait_group 0;" ::: "memory");
        __syncthreads();
        if (MODE == 1 && i + 1 < 8) ldB(i + 1);

        const uint32_t tAh = sb + SM_TILE(s, 0);
        const uint32_t tBh = sb + SM_TILE(s, 1);
#pragma unroll
        for (int ks = 0; ks < 2; ks++) {
            const int kh = ks * 16;
            uint32_t aH[4][4], bH[4][2];
#pragma unroll
            for (int mt = 0; mt < 4; mt++) {
                uint32_t off = (uint32_t)(m0w + mt * 16 + a_row) * PITCH + (kh + a_colh) * 2;
                ldsm4(aH[mt], tAh + off);
            }
#pragma unroll
            for (int bt = 0; bt < 2; bt++) {
                uint32_t off = (uint32_t)(n0w + bt * 16 + b_row) * PITCH + (kh + b_colh) * 2;
                uint32_t rh[4];
                ldsm4(rh, tBh + off);
                bH[bt * 2][0] = rh[0]; bH[bt * 2][1] = rh[1];
                bH[bt * 2 + 1][0] = rh[2]; bH[bt * 2 + 1][1] = rh[3];
            }
#pragma unroll
            for (int mt = 0; mt < 4; mt++)
#pragma unroll
                for (int nt = 0; nt < 4; nt++)
                    mma16816(acc[mt][nt], aH[mt], bH[nt][0], bH[nt][1]);
        }
        __syncthreads();
        if (i + 2 < 8) { if (MODE == 0) load2(i + 2, s); else loadA(i + 2, s); }
    }

    if (MODE == 0) {
        // transposed epilogue via smem: sT[px][ch] (pitch 132 floats)
        float* sT = (float*)smem;
        __syncthreads();
#pragma unroll
        for (int mt = 0; mt < 4; mt++) {
            int rr0 = m0w + mt * 16 + (lane >> 2);
            int rr1 = rr0 + 8;
            float b0 = d_ball[mbase + rr0], b1 = d_ball[mbase + rr1];
#pragma unroll
            for (int nt = 0; nt < 4; nt++) {
                int cc = n0w + nt * 8 + (lane & 3) * 2;
                sT[(cc) * 132 + rr0]     = acc[mt][nt][0] + b0;
                sT[(cc + 1) * 132 + rr0] = acc[mt][nt][1] + b0;
                sT[(cc) * 132 + rr1]     = acc[mt][nt][2] + b1;
                sT[(cc + 1) * 132 + rr1] = acc[mt][nt][3] + b1;
            }
        }
        __syncthreads();
#pragma unroll
        for (int j = 0; j < 16; j++) {
            int idx = tid + j * 256;
            int px = idx >> 5, c4 = idx & 31;
            float4 v = *(float4*)&sT[px * 132 + c4 * 4];
            __half2* dst = (__half2*)&d_qkvT[((size_t)b * HW + nbase + px) * 1024 + mbase + c4 * 4];
            dst[0] = __floats2half2_rn(v.x, v.y);
            dst[1] = __floats2half2_rn(v.z, v.w);
        }
        if (mbase < 512 && tid < 128) {
            int px = tid;
            float s = 0.f;
#pragma unroll
            for (int c4 = 0; c4 < 32; c4++) {
                float4 v = *(float4*)&sT[px * 132 + c4 * 4];
                s += v.x * v.x + v.y * v.y + v.z * v.z + v.w * v.w;
            }
            d_ssqp[(size_t)(mbase >> 7) * (B_ * HW) + b * HW + nbase + px] = s;
        }
    } else {
        float* Cg = CoutExt + (size_t)b * 256 * HW;
#pragma unroll
        for (int mt = 0; mt < 4; mt++) {
            int r0 = mbase + m0w + mt * 16 + (lane >> 2);
            int r1 = r0 + 8;
            float sc0 = d_s[r0], t0 = d_t[r0], sc1 = d_s[r1], t1 = d_t[r1];
#pragma unroll
            for (int nt = 0; nt < 4; nt++) {
                int c = nbase + n0w + nt * 8 + (lane & 3) * 2;
                float2 o0, o1;
                o0.x = fmaxf(acc[mt][nt][0] * sc0 + t0, 0.f);
                o0.y = fmaxf(acc[mt][nt][1] * sc0 + t0, 0.f);
                o1.x = fmaxf(acc[mt][nt][2] * sc1 + t1, 0.f);
                o1.y = fmaxf(acc[mt][nt][3] * sc1 + t1, 0.f);
                *(float2*)&Cg[(size_t)r0 * HW + c] = o0;
                *(float2*)&Cg[(size_t)r1 * HW + c] = o1;
            }
        }
    }
}

// ---------------- K2s: finish pixelnorm factors --------------------------------
__global__ void k2s() {
    int i = blockIdx.x * blockDim.x + threadIdx.x;
    float sq = d_ssqp[i] + d_ssqp[B_ * HW + i];
    float sk = d_ssqp[2 * B_ * HW + i] + d_ssqp[3 * B_ * HW + i];
    d_invq[i] = rsqrtf(sq * (1.f / 256.f) + 1e-8f);
    d_invk[i] = rsqrtf(sk * (1.f / 256.f) + 1e-8f);
}

// ---------------- K3a: per-head partial kv = (k*invk) @ v^T (fp16 src) ---------
__global__ __launch_bounds__(256) void k3a_kv() {
    int head = blockIdx.y, split = blockIdx.x;
    int b = head >> 3, h = head & 7;

    __shared__ float ks[128][32];
    __shared__ float vs[128][64];

    int tid = threadIdx.x;
    int tx = tid & 15, ty = tid >> 4;
    float acc[2][4] = {};

    for (int it = 0; it < 4; it++) {
        int pb = split * 512 + it * 128;
        // k: 128 px x 32 ch halves = 512 uint4-groups of 8 halves
#pragma unroll
        for (int j = 0; j < 2; j++) {
            int idx = tid + j * 256;
            int r = idx >> 2, c8 = idx & 3;
            int p = pb + r;
            float iv = d_invk[b * HW + p];
            const __half2* src = (const __half2*)&d_qkvT[((size_t)b * HW + p) * 1024 + 256 + h * 32 + c8 * 8];
#pragma unroll
            for (int u = 0; u < 4; u++) {
                float2 v = __half22float2(src[u]);
                ks[r][c8 * 8 + u * 2]     = v.x * iv;
                ks[r][c8 * 8 + u * 2 + 1] = v.y * iv;
            }
        }
        // v: 128 px x 64 ch halves
#pragma unroll
        for (int j = 0; j < 4; j++) {
            int idx = tid + j * 256;
            int r = idx >> 3, c8 = idx & 7;
            int p = pb + r;
            const __half2* src = (const __half2*)&d_qkvT[((size_t)b * HW + p) * 1024 + 512 + h * 64 + c8 * 8];
#pragma unroll
            for (int u = 0; u < 4; u++) {
                float2 v = __half22float2(src[u]);
                vs[r][c8 * 8 + u * 2]     = v.x;
                vs[r][c8 * 8 + u * 2 + 1] = v.y;
            }
        }
        __syncthreads();
#pragma unroll 4
        for (int p = 0; p < 128; p++) {
            float4 v4 = *(const float4*)&vs[p][tx * 4];
            float k0 = ks[p][ty * 2], k1 = ks[p][ty * 2 + 1];
            acc[0][0] += k0 * v4.x; acc[0][1] += k0 * v4.y;
            acc[0][2] += k0 * v4.z; acc[0][3] += k0 * v4.w;
            acc[1][0] += k1 * v4.x; acc[1][1] += k1 * v4.y;
            acc[1][2] += k1 * v4.z; acc[1][3] += k1 * v4.w;
        }
        __syncthreads();
    }
    float* out = d_kvpart + ((size_t)head * 8 + split) * 2048;
#pragma unroll
    for (int i = 0; i < 2; i++)
#pragma unroll
        for (int j = 0; j < 4; j++)
            out[(ty * 2 + i) * 64 + tx * 4 + j] = acc[i][j];
}

// ---------------- K3b: reduce kv, pixelnorm, m, Wf2 (writes fp16) --------------
__global__ __launch_bounds__(256) void k3b_kvnorm(const float* __restrict__ Wf) {
    int head = blockIdx.x;
    int b = head >> 3, h = head & 7;
    __shared__ float skv[2048];
    __shared__ float nrm[64];
    int tid = threadIdx.x;
#pragma unroll
    for (int s = 0; s < 8; s++) {
        int idx = tid + s * 256;
        float sum = 0.f;
#pragma unroll
        for (int sp = 0; sp < 8; sp++)
            sum += d_kvpart[(size_t)(head * 8 + sp) * 2048 + idx];
        skv[idx] = sum;
    }
    __syncthreads();
    if (tid < 64) {
        float s = 0.f;
#pragma unroll
        for (int c = 0; c < 32; c++) { float v = skv[c * 64 + tid]; s += v * v; }
        nrm[tid] = rsqrtf(s * (1.f / 32.f) + 1e-8f);
    }
    __syncthreads();
#pragma unroll
    for (int s = 0; s < 8; s++) {
        int idx = tid + s * 256;
        skv[idx] *= nrm[idx & 63];
    }
    __syncthreads();
    if (tid < 32) {
        float s = 0.f;
#pragma unroll
        for (int C = 32; C < 64; C++) s += skv[tid * 64 + C];
        d_m[head * 32 + tid] = s * (1.f / 32.f);
    }
    int o = tid;
    float wf[32];
#pragma unroll
    for (int c2 = 0; c2 < 32; c2++) wf[c2] = Wf[o * 256 + h * 32 + c2];
    size_t ob = (size_t)b * 65536 + o * 256 + h * 32;
    for (int c = 0; c < 32; c++) {
        float s = 0.f;
#pragma unroll
        for (int c2 = 0; c2 < 32; c2++) s += wf[c2] * skv[c * 64 + c2];
        d_W2_h[ob + c] = __float2half(s);
    }
}

// ---------------- K4: spatial softmax gate (fp16 q) ----------------------------
__global__ __launch_bounds__(1024) void k4_gate() {
    int head = blockIdx.x;
    int b = head >> 3, h = head & 7;
    __shared__ float sm[32];
    __shared__ float red[1024];
    int tid = threadIdx.x;
    if (tid < 32) sm[tid] = d_m[head * 32 + tid];
    __syncthreads();

    float z[4];
    float lmax = -1e30f;
#pragma unroll
    for (int i = 0; i < 4; i++) {
        int p = tid + i * 1024;
        const __half2* row = (const __half2*)&d_qkvT[((size_t)b * HW + p) * 1024 + h * 32];
        float s = 0.f;
#pragma unroll
        for (int c2 = 0; c2 < 16; c2++) {
            float2 q = __half22float2(row[c2]);
            s += q.x * sm[c2 * 2] + q.y * sm[c2 * 2 + 1];
        }
        z[i] = s * d_invq[b * HW + p] * (1.f / 64.f);
        lmax = fmaxf(lmax, z[i]);
    }
    red[tid] = lmax; __syncthreads();
    for (int st = 512; st > 0; st >>= 1) {
        if (tid < st) red[tid] = fmaxf(red[tid], red[tid + st]);
        __syncthreads();
    }
    float gmax = red[0]; __syncthreads();
    float lsum = 0.f;
#pragma unroll
    for (int i = 0; i < 4; i++) { z[i] = __expf(z[i] - gmax); lsum += z[i]; }
    red[tid] = lsum; __syncthreads();
    for (int st = 512; st > 0; st >>= 1) {
        if (tid < st) red[tid] += red[tid + st];
        __syncthreads();
    }
    float inv = 1.f / red[0];
#pragma unroll
    for (int i = 0; i < 4; i++)
        d_gate[(size_t)head * HW + tid + i * 1024] = z[i] * inv;
}

// ---------------- launch --------------------------------------------------------
extern "C" void kernel_launch(void* const* d_in, const int* in_sizes, int n_in,
                              void* d_out, int out_size) {
    const float* x     = (const float*)d_in[0];
    const float* Wq    = (const float*)d_in[1];
    const float* bq    = (const float*)d_in[2];
    const float* Wk    = (const float*)d_in[3];
    const float* bk    = (const float*)d_in[4];
    const float* Wv    = (const float*)d_in[5];
    const float* bv    = (const float*)d_in[6];
    const float* Wf    = (const float*)d_in[7];
    const float* bf    = (const float*)d_in[8];
    const float* gamma = (const float*)d_in[9];
    const float* beta  = (const float*)d_in[10];
    const float* mean  = (const float*)d_in[11];
    const float* var   = (const float*)d_in[12];
    float* out = (float*)d_out;

    static bool attr_set = false;
    if (!attr_set) {
        cudaFuncSetAttribute(k_mma<0>, cudaFuncAttributeMaxDynamicSharedMemorySize, SMEM_SZ);
        cudaFuncSetAttribute(k_mma<1>, cudaFuncAttributeMaxDynamicSharedMemorySize, SMEM_SZ);
        attr_set = true;
    }

    k0_prep<<<(1024 * 256 + 255) / 256, 256>>>(Wq, bq, Wk, bk, Wv, bv, bf, gamma, beta, mean, var);
    k_convx<<<dim3(128, 4, B_), 256>>>(x);
    k_mma<0><<<dim3(32, 8, B_), 256, SMEM_SZ>>>(nullptr);
    k2s<<<256, 128>>>();
    k3a_kv<<<dim3(8, 64), 256>>>();
    k3b_kvnorm<<<64, 256>>>(Wf);
    k4_gate<<<64, 1024>>>();
    k_mma<1><<<dim3(32, 2, B_), 256, SMEM_SZ>>>(out);
}

// round 8
// speedup vs baseline: 1.4803x; 1.1137x over previous
#include <cuda_runtime.h>
#include <cuda_fp16.h>
#include <cstdint>

#define HW 4096
#define B_ 8

// ---------------- scratch -----------------------------------------------------
__device__ __half d_qkvT[(size_t)B_ * HW * 1024];  // pixel-major fp16: [b][p][ch]
__device__ float d_ssqp[4 * B_ * HW];              // partial ssq tiles q0,q1,k0,k1
__device__ float d_invq[B_ * HW];
__device__ float d_invk[B_ * HW];
__device__ float d_kvpart[64 * 8 * 2048];
__device__ float d_m[64 * 32];
__device__ float d_gate[64 * HW];
__device__ float d_ball[1024];
__device__ float d_s[256];
__device__ float d_t[256];
__device__ __half d_Wq_h[1024 * 256];
__device__ __half d_xT_h[(size_t)B_ * HW * 256];
__device__ __half d_W2_h[B_ * 256 * 256];

// ---------------- helpers -------------------------------------------------------
__device__ __forceinline__ uint32_t smem_u32(const void* p) {
    uint32_t a;
    asm("{ .reg .u64 t; cvta.to.shared.u64 t, %1; cvt.u32.u64 %0, t; }" : "=r"(a) : "l"(p));
    return a;
}
__device__ __forceinline__ void cp16(uint32_t dst, const void* src) {
    asm volatile("cp.async.cg.shared.global [%0], [%1], 16;" :: "r"(dst), "l"(src));
}
#define CP_COMMIT() asm volatile("cp.async.commit_group;" ::: "memory")

__device__ __forceinline__ void ldsm4(uint32_t* r, uint32_t addr) {
    asm volatile("ldmatrix.sync.aligned.m8n8.x4.shared.b16 {%0,%1,%2,%3}, [%4];"
        : "=r"(r[0]), "=r"(r[1]), "=r"(r[2]), "=r"(r[3]) : "r"(addr));
}
__device__ __forceinline__ void mma16816(float* d, const uint32_t* a, uint32_t b0, uint32_t b1) {
    asm volatile("mma.sync.aligned.m16n8k16.row.col.f32.f16.f16.f32 "
        "{%0,%1,%2,%3}, {%4,%5,%6,%7}, {%8,%9}, {%0,%1,%2,%3};"
        : "+f"(d[0]), "+f"(d[1]), "+f"(d[2]), "+f"(d[3])
        : "r"(a[0]), "r"(a[1]), "r"(a[2]), "r"(a[3]), "r"(b0), "r"(b1));
}

// ---------------- K0: pack weights fp16, biases, BN fold -----------------------
__global__ void k0_prep(const float* __restrict__ Wq, const float* __restrict__ bq,
                        const float* __restrict__ Wk, const float* __restrict__ bk,
                        const float* __restrict__ Wv, const float* __restrict__ bv,
                        const float* __restrict__ bf,
                        const float* __restrict__ gamma, const float* __restrict__ beta,
                        const float* __restrict__ mean,  const float* __restrict__ var) {
    int idx = blockIdx.x * blockDim.x + threadIdx.x;
    if (idx < 1024 * 256) {
        int r = idx >> 8, c = idx & 255;
        float w = (r < 256) ? Wq[r * 256 + c] : (r < 512) ? Wk[(r - 256) * 256 + c] : Wv[(r - 512) * 256 + c];
        d_Wq_h[idx] = __float2half(w);
    }
    if (idx < 1024)
        d_ball[idx] = (idx < 256) ? bq[idx] : (idx < 512) ? bk[idx - 256] : bv[idx - 512];
    if (idx < 256) {
        float s = gamma[idx] * rsqrtf(var[idx] + 1e-5f);
        d_s[idx] = s;
        d_t[idx] = (bf[idx] - mean[idx]) * s + beta[idx];
    }
}

// ---------------- convert x -> xT fp16 (transpose) -----------------------------
__global__ __launch_bounds__(256) void k_convx(const float* __restrict__ x) {
    __shared__ float t[64][33];
    int p0 = blockIdx.x * 32, c0 = blockIdx.y * 64, b = blockIdx.z;
    const float* src = x + ((size_t)b * 256 + c0) * HW + p0;
    int tid = threadIdx.x;
#pragma unroll
    for (int j = 0; j < 8; j++) {
        int idx = tid + j * 256;
        int cc = idx >> 5, pp = idx & 31;
        t[cc][pp] = src[(size_t)cc * HW + pp];
    }
    __syncthreads();
    __half2* oh = (__half2*)d_xT_h;
#pragma unroll
    for (int j = 0; j < 4; j++) {
        int idx = tid + j * 256;
        int p = idx >> 5, pr = idx & 31;
        oh[((size_t)b * HW + p0 + p) * 128 + (c0 >> 1) + pr] =
            __floats2half2_rn(t[pr * 2][p], t[pr * 2 + 1][p]);
    }
}

// ---------------- mma.sync GEMM (fp16 single-term) -----------------------------
// MODE 0: qkv = Wqkv @ x^T  -> writes d_qkvT (fp16, transposed) + partial ssq
// MODE 1: out = Wf2 @ z^T   -> B operand (z = gate*invq*q) folded in loader
// Block 128x128, 8 warps (2x4), warp tile 64x32, K-chunk 32, 2-stage cp.async,
// 2 CTAs/SM for cross-CTA latency hiding.
#define PITCH 80
#define TILE_BYTES (128 * PITCH)
#define SM_TILE(s, t) (((s) * 2 + (t)) * TILE_BYTES)
#define SMEM_SZ0 69632
#define SMEM_SZ1 40960

template <int MODE>
__global__ __launch_bounds__(256, 2) void k_mma(float* __restrict__ CoutExt) {
    extern __shared__ char smem[];
    uint32_t sb = smem_u32(smem);
    const int tid = threadIdx.x;
    const int lane = tid & 31;
    const int wid = tid >> 5;
    const int wm = wid >> 2, wn = wid & 3;
    const int m0w = wm * 64, n0w = wn * 32;
    const int b = blockIdx.z;
    const int nbase = blockIdx.x * 128;
    const int mbase = blockIdx.y * 128;

    const __half* Ah = (MODE == 0) ? d_Wq_h + (size_t)mbase * 256
                                   : d_W2_h + (size_t)b * 65536 + (size_t)mbase * 256;
    const __half* Bh = d_xT_h + (size_t)b * HW * 256 + (size_t)nbase * 256;

    const __half* bases2[2] = {Ah, Bh};

    // MODE 0: 2 tiles x 128 rows x 4 chunks(16B) = 1024 / 256 thr = 4 each
    auto load2 = [&](int kc, int s) {
#pragma unroll
        for (int j = 0; j < 4; j++) {
            int g = tid + j * 256;
            int t = g >> 9, w = g & 511;
            int r = w >> 2, c = w & 3;
            const char* src = (const char*)bases2[t] + ((size_t)r * 256 + kc * 32 + c * 8) * 2;
            cp16(sb + SM_TILE(s, t) + r * PITCH + c * 16, src);
        }
        CP_COMMIT();
    };
    // MODE 1: A tile only (512 chunks / 256 = 2 each)
    auto loadA = [&](int kc, int s) {
#pragma unroll
        for (int j = 0; j < 2; j++) {
            int g = tid + j * 256;
            int r = g >> 2, c = g & 3;
            const char* src = (const char*)Ah + ((size_t)r * 256 + kc * 32 + c * 8) * 2;
            cp16(sb + SM_TILE(s, 0) + r * PITCH + c * 16, src);
        }
        CP_COMMIT();
    };

    // MODE 1: B chunk fp16 load + fold gate*invq (chunk kc == head kc)
    float fpx[2];
    float breg[2][8];
    auto ldB = [&](int kc) {
#pragma unroll
        for (int j = 0; j < 2; j++) {
            int idx = tid + j * 256;              // 0..511
            int r = idx >> 2, c8 = idx & 3;       // px, group of 8 halves
            int p = nbase + r;
            float f = fpx[j] * d_gate[(size_t)(b * 8 + kc) * HW + p];
            const __half2* src = (const __half2*)&d_qkvT[((size_t)b * HW + p) * 1024 + kc * 32 + c8 * 8];
#pragma unroll
            for (int u = 0; u < 4; u++) {
                float2 v = __half22float2(src[u]);
                breg[j][u * 2]     = v.x * f;
                breg[j][u * 2 + 1] = v.y * f;
            }
        }
    };
    auto stB = [&](int s) {
#pragma unroll
        for (int j = 0; j < 2; j++) {
            int idx = tid + j * 256;
            int r = idx >> 2, c8 = idx & 3;
            __half2* dst = (__half2*)(smem + SM_TILE(s, 1) + r * PITCH + c8 * 16);
#pragma unroll
            for (int u = 0; u < 4; u++)
                dst[u] = __floats2half2_rn(breg[j][u * 2], breg[j][u * 2 + 1]);
        }
    };

    float acc[4][4][4] = {};
    const int a_row = lane & 15;
    const int a_colh = (lane >> 4) << 3;
    const int b_row = (lane & 7) + ((lane >> 4) << 3);
    const int b_colh = ((lane >> 3) & 1) << 3;

    if (MODE == 0) {
        load2(0, 0); load2(1, 1);
    } else {
#pragma unroll
        for (int j = 0; j < 2; j++)
            fpx[j] = d_invq[b * HW + nbase + ((tid + j * 256) >> 2)];
        loadA(0, 0); loadA(1, 1);
        ldB(0);
    }

#pragma unroll
    for (int i = 0; i < 8; i++) {
        const int s = i & 1;
        if (MODE == 1) stB(s);
        if (i < 6) asm volatile("cp.async.wait_group 1;" ::: "memory");
        else       asm volatile("cp.async.wait_group 0;" ::: "memory");
        __syncthreads();
        if (MODE == 1 && i + 1 < 8) ldB(i + 1);

        const uint32_t tAh = sb + SM_TILE(s, 0);
        const uint32_t tBh = sb + SM_TILE(s, 1);
#pragma unroll
        for (int ks = 0; ks < 2; ks++) {
            const int kh = ks * 16;
            uint32_t aH[4][4], bH[4][2];
#pragma unroll
            for (int mt = 0; mt < 4; mt++) {
                uint32_t off = (uint32_t)(m0w + mt * 16 + a_row) * PITCH + (kh + a_colh) * 2;
                ldsm4(aH[mt], tAh + off);
            }
#pragma unroll
            for (int bt = 0; bt < 2; bt++) {
                uint32_t off = (uint32_t)(n0w + bt * 16 + b_row) * PITCH + (kh + b_colh) * 2;
                uint32_t rh[4];
                ldsm4(rh, tBh + off);
                bH[bt * 2][0] = rh[0]; bH[bt * 2][1] = rh[1];
                bH[bt * 2 + 1][0] = rh[2]; bH[bt * 2 + 1][1] = rh[3];
            }
#pragma unroll
            for (int mt = 0; mt < 4; mt++)
#pragma unroll
                for (int nt = 0; nt < 4; nt++)
                    mma16816(acc[mt][nt], aH[mt], bH[nt][0], bH[nt][1]);
        }
        __syncthreads();
        if (i + 2 < 8) { if (MODE == 0) load2(i + 2, s); else loadA(i + 2, s); }
    }

    if (MODE == 0) {
        // transposed epilogue via smem: sT[px][ch] (pitch 132 floats)
        float* sT = (float*)smem;
        __syncthreads();
#pragma unroll
        for (int mt = 0; mt < 4; mt++) {
            int rr0 = m0w + mt * 16 + (lane >> 2);
            int rr1 = rr0 + 8;
            float b0 = d_ball[mbase + rr0], b1 = d_ball[mbase + rr1];
#pragma unroll
            for (int nt = 0; nt < 4; nt++) {
                int cc = n0w + nt * 8 + (lane & 3) * 2;
                sT[(cc) * 132 + rr0]     = acc[mt][nt][0] + b0;
                sT[(cc + 1) * 132 + rr0] = acc[mt][nt][1] + b0;
                sT[(cc) * 132 + rr1]     = acc[mt][nt][2] + b1;
                sT[(cc + 1) * 132 + rr1] = acc[mt][nt][3] + b1;
            }
        }
        __syncthreads();
#pragma unroll
        for (int j = 0; j < 16; j++) {
            int idx = tid + j * 256;
            int px = idx >> 5, c4 = idx & 31;
            float4 v = *(float4*)&sT[px * 132 + c4 * 4];
            __half2* dst = (__half2*)&d_qkvT[((size_t)b * HW + nbase + px) * 1024 + mbase + c4 * 4];
            dst[0] = __floats2half2_rn(v.x, v.y);
            dst[1] = __floats2half2_rn(v.z, v.w);
        }
        if (mbase < 512 && tid < 128) {
            int px = tid;
            float s = 0.f;
#pragma unroll
            for (int c4 = 0; c4 < 32; c4++) {
                float4 v = *(float4*)&sT[px * 132 + c4 * 4];
                s += v.x * v.x + v.y * v.y + v.z * v.z + v.w * v.w;
            }
            d_ssqp[(size_t)(mbase >> 7) * (B_ * HW) + b * HW + nbase + px] = s;
        }
    } else {
        float* Cg = CoutExt + (size_t)b * 256 * HW;
#pragma unroll
        for (int mt = 0; mt < 4; mt++) {
            int r0 = mbase + m0w + mt * 16 + (lane >> 2);
            int r1 = r0 + 8;
            float sc0 = d_s[r0], t0 = d_t[r0], sc1 = d_s[r1], t1 = d_t[r1];
#pragma unroll
            for (int nt = 0; nt < 4; nt++) {
                int c = nbase + n0w + nt * 8 + (lane & 3) * 2;
                float2 o0, o1;
                o0.x = fmaxf(acc[mt][nt][0] * sc0 + t0, 0.f);
                o0.y = fmaxf(acc[mt][nt][1] * sc0 + t0, 0.f);
                o1.x = fmaxf(acc[mt][nt][2] * sc1 + t1, 0.f);
                o1.y = fmaxf(acc[mt][nt][3] * sc1 + t1, 0.f);
                *(float2*)&Cg[(size_t)r0 * HW + c] = o0;
                *(float2*)&Cg[(size_t)r1 * HW + c] = o1;
            }
        }
    }
}

// ---------------- K2s: finish pixelnorm factors --------------------------------
__global__ void k2s() {
    int i = blockIdx.x * blockDim.x + threadIdx.x;
    float sq = d_ssqp[i] + d_ssqp[B_ * HW + i];
    float sk = d_ssqp[2 * B_ * HW + i] + d_ssqp[3 * B_ * HW + i];
    d_invq[i] = rsqrtf(sq * (1.f / 256.f) + 1e-8f);
    d_invk[i] = rsqrtf(sk * (1.f / 256.f) + 1e-8f);
}

// ---------------- K3a: per-head partial kv = (k*invk) @ v^T (fp16 src) ---------
__global__ __launch_bounds__(256) void k3a_kv() {
    int head = blockIdx.y, split = blockIdx.x;
    int b = head >> 3, h = head & 7;

    __shared__ float ks[128][32];
    __shared__ float vs[128][64];

    int tid = threadIdx.x;
    int tx = tid & 15, ty = tid >> 4;
    float acc[2][4] = {};

    for (int it = 0; it < 4; it++) {
        int pb = split * 512 + it * 128;
#pragma unroll
        for (int j = 0; j < 2; j++) {
            int idx = tid + j * 256;
            int r = idx >> 2, c8 = idx & 3;
            int p = pb + r;
            float iv = d_invk[b * HW + p];
            const __half2* src = (const __half2*)&d_qkvT[((size_t)b * HW + p) * 1024 + 256 + h * 32 + c8 * 8];
#pragma unroll
            for (int u = 0; u < 4; u++) {
                float2 v = __half22float2(src[u]);
                ks[r][c8 * 8 + u * 2]     = v.x * iv;
                ks[r][c8 * 8 + u * 2 + 1] = v.y * iv;
            }
        }
#pragma unroll
        for (int j = 0; j < 4; j++) {
            int idx = tid + j * 256;
            int r = idx >> 3, c8 = idx & 7;
            int p = pb + r;
            const __half2* src = (const __half2*)&d_qkvT[((size_t)b * HW + p) * 1024 + 512 + h * 64 + c8 * 8];
#pragma unroll
            for (int u = 0; u < 4; u++) {
                float2 v = __half22float2(src[u]);
                vs[r][c8 * 8 + u * 2]     = v.x;
                vs[r][c8 * 8 + u * 2 + 1] = v.y;
            }
        }
        __syncthreads();
#pragma unroll 4
        for (int p = 0; p < 128; p++) {
            float4 v4 = *(const float4*)&vs[p][tx * 4];
            float k0 = ks[p][ty * 2], k1 = ks[p][ty * 2 + 1];
            acc[0][0] += k0 * v4.x; acc[0][1] += k0 * v4.y;
            acc[0][2] += k0 * v4.z; acc[0][3] += k0 * v4.w;
            acc[1][0] += k1 * v4.x; acc[1][1] += k1 * v4.y;
            acc[1][2] += k1 * v4.z; acc[1][3] += k1 * v4.w;
        }
        __syncthreads();
    }
    float* out = d_kvpart + ((size_t)head * 8 + split) * 2048;
#pragma unroll
    for (int i = 0; i < 2; i++)
#pragma unroll
        for (int j = 0; j < 4; j++)
            out[(ty * 2 + i) * 64 + tx * 4 + j] = acc[i][j];
}

// ---------------- K3b: reduce kv, pixelnorm, m, Wf2 (writes fp16) --------------
__global__ __launch_bounds__(256) void k3b_kvnorm(const float* __restrict__ Wf) {
    int head = blockIdx.x;
    int b = head >> 3, h = head & 7;
    __shared__ float skv[2048];
    __shared__ float nrm[64];
    int tid = threadIdx.x;
#pragma unroll
    for (int s = 0; s < 8; s++) {
        int idx = tid + s * 256;
        float sum = 0.f;
#pragma unroll
        for (int sp = 0; sp < 8; sp++)
            sum += d_kvpart[(size_t)(head * 8 + sp) * 2048 + idx];
        skv[idx] = sum;
    }
    __syncthreads();
    if (tid < 64) {
        float s = 0.f;
#pragma unroll
        for (int c = 0; c < 32; c++) { float v = skv[c * 64 + tid]; s += v * v; }
        nrm[tid] = rsqrtf(s * (1.f / 32.f) + 1e-8f);
    }
    __syncthreads();
#pragma unroll
    for (int s = 0; s < 8; s++) {
        int idx = tid + s * 256;
        skv[idx] *= nrm[idx & 63];
    }
    __syncthreads();
    if (tid < 32) {
        float s = 0.f;
#pragma unroll
        for (int C = 32; C < 64; C++) s += skv[tid * 64 + C];
        d_m[head * 32 + tid] = s * (1.f / 32.f);
    }
    int o = tid;
    float wf[32];
#pragma unroll
    for (int c2 = 0; c2 < 32; c2++) wf[c2] = Wf[o * 256 + h * 32 + c2];
    size_t ob = (size_t)b * 65536 + o * 256 + h * 32;
    for (int c = 0; c < 32; c++) {
        float s = 0.f;
#pragma unroll
        for (int c2 = 0; c2 < 32; c2++) s += wf[c2] * skv[c * 64 + c2];
        d_W2_h[ob + c] = __float2half(s);
    }
}

// ---------------- K4: spatial softmax gate (fp16 q) ----------------------------
__global__ __launch_bounds__(1024) void k4_gate() {
    int head = blockIdx.x;
    int b = head >> 3, h = head & 7;
    __shared__ float sm[32];
    __shared__ float red[1024];
    int tid = threadIdx.x;
    if (tid < 32) sm[tid] = d_m[head * 32 + tid];
    __syncthreads();

    float z[4];
    float lmax = -1e30f;
#pragma unroll
    for (int i = 0; i < 4; i++) {
        int p = tid + i * 1024;
        const __half2* row = (const __half2*)&d_qkvT[((size_t)b * HW + p) * 1024 + h * 32];
        float s = 0.f;
#pragma unroll
        for (int c2 = 0; c2 < 16; c2++) {
            float2 q = __half22float2(row[c2]);
            s += q.x * sm[c2 * 2] + q.y * sm[c2 * 2 + 1];
        }
        z[i] = s * d_invq[b * HW + p] * (1.f / 64.f);
        lmax = fmaxf(lmax, z[i]);
    }
    red[tid] = lmax; __syncthreads();
    for (int st = 512; st > 0; st >>= 1) {
        if (tid < st) red[tid] = fmaxf(red[tid], red[tid + st]);
        __syncthreads();
    }
    float gmax = red[0]; __syncthreads();
    float lsum = 0.f;
#pragma unroll
    for (int i = 0; i < 4; i++) { z[i] = __expf(z[i] - gmax); lsum += z[i]; }
    red[tid] = lsum; __syncthreads();
    for (int st = 512; st > 0; st >>= 1) {
        if (tid < st) red[tid] += red[tid + st];
        __syncthreads();
    }
    float inv = 1.f / red[0];
#pragma unroll
    for (int i = 0; i < 4; i++)
        d_gate[(size_t)head * HW + tid + i * 1024] = z[i] * inv;
}

// ---------------- launch --------------------------------------------------------
extern "C" void kernel_launch(void* const* d_in, const int* in_sizes, int n_in,
                              void* d_out, int out_size) {
    const float* x     = (const float*)d_in[0];
    const float* Wq    = (const float*)d_in[1];
    const float* bq    = (const float*)d_in[2];
    const float* Wk    = (const float*)d_in[3];
    const float* bk    = (const float*)d_in[4];
    const float* Wv    = (const float*)d_in[5];
    const float* bv    = (const float*)d_in[6];
    const float* Wf    = (const float*)d_in[7];
    const float* bf    = (const float*)d_in[8];
    const float* gamma = (const float*)d_in[9];
    const float* beta  = (const float*)d_in[10];
    const float* mean  = (const float*)d_in[11];
    const float* var   = (const float*)d_in[12];
    float* out = (float*)d_out;

    static bool attr_set = false;
    if (!attr_set) {
        cudaFuncSetAttribute(k_mma<0>, cudaFuncAttributeMaxDynamicSharedMemorySize, SMEM_SZ0);
        cudaFuncSetAttribute(k_mma<1>, cudaFuncAttributeMaxDynamicSharedMemorySize, SMEM_SZ1);
        attr_set = true;
    }

    k0_prep<<<(1024 * 256 + 255) / 256, 256>>>(Wq, bq, Wk, bk, Wv, bv, bf, gamma, beta, mean, var);
    k_convx<<<dim3(128, 4, B_), 256>>>(x);
    k_mma<0><<<dim3(32, 8, B_), 256, SMEM_SZ0>>>(nullptr);
    k2s<<<256, 128>>>();
    k3a_kv<<<dim3(8, 64), 256>>>();
    k3b_kvnorm<<<64, 256>>>(Wf);
    k4_gate<<<64, 1024>>>();
    k_mma<1><<<dim3(32, 2, B_), 256, SMEM_SZ1>>>(out);
}

// round 9
// speedup vs baseline: 1.5274x; 1.0318x over previous
#include <cuda_runtime.h>
#include <cuda_fp16.h>
#include <cstdint>

#define HW 4096
#define B_ 8

// ---------------- scratch -----------------------------------------------------
__device__ __half d_qkvT[(size_t)B_ * HW * 1024];  // pixel-major fp16: [b][p][ch]
__device__ float d_ssqp[4 * B_ * HW];              // partial ssq tiles q0,q1,k0,k1
__device__ float d_invq[B_ * HW];
__device__ float d_invk[B_ * HW];
__device__ float d_kvpart[64 * 8 * 2048];
__device__ float d_m[64 * 32];
__device__ float d_gate[64 * HW];
__device__ float d_ball[1024];
__device__ float d_s[256];
__device__ float d_t[256];
__device__ __half d_Wq_h[1024 * 256];
__device__ __half d_xT_h[(size_t)B_ * HW * 256];
__device__ __half d_W2_h[B_ * 256 * 256];

// ---------------- helpers -------------------------------------------------------
__device__ __forceinline__ uint32_t smem_u32(const void* p) {
    uint32_t a;
    asm("{ .reg .u64 t; cvta.to.shared.u64 t, %1; cvt.u32.u64 %0, t; }" : "=r"(a) : "l"(p));
    return a;
}
__device__ __forceinline__ void cp16(uint32_t dst, const void* src) {
    asm volatile("cp.async.cg.shared.global [%0], [%1], 16;" :: "r"(dst), "l"(src));
}
#define CP_COMMIT() asm volatile("cp.async.commit_group;" ::: "memory")

__device__ __forceinline__ void ldsm4(uint32_t* r, uint32_t addr) {
    asm volatile("ldmatrix.sync.aligned.m8n8.x4.shared.b16 {%0,%1,%2,%3}, [%4];"
        : "=r"(r[0]), "=r"(r[1]), "=r"(r[2]), "=r"(r[3]) : "r"(addr));
}
__device__ __forceinline__ void mma16816(float* d, const uint32_t* a, uint32_t b0, uint32_t b1) {
    asm volatile("mma.sync.aligned.m16n8k16.row.col.f32.f16.f16.f32 "
        "{%0,%1,%2,%3}, {%4,%5,%6,%7}, {%8,%9}, {%0,%1,%2,%3};"
        : "+f"(d[0]), "+f"(d[1]), "+f"(d[2]), "+f"(d[3])
        : "r"(a[0]), "r"(a[1]), "r"(a[2]), "r"(a[3]), "r"(b0), "r"(b1));
}

// ---------------- K0: pack weights fp16, biases, BN fold -----------------------
__global__ void k0_prep(const float* __restrict__ Wq, const float* __restrict__ bq,
                        const float* __restrict__ Wk, const float* __restrict__ bk,
                        const float* __restrict__ Wv, const float* __restrict__ bv,
                        const float* __restrict__ bf,
                        const float* __restrict__ gamma, const float* __restrict__ beta,
                        const float* __restrict__ mean,  const float* __restrict__ var) {
    int idx = blockIdx.x * blockDim.x + threadIdx.x;
    if (idx < 1024 * 256) {
        int r = idx >> 8, c = idx & 255;
        float w = (r < 256) ? Wq[r * 256 + c] : (r < 512) ? Wk[(r - 256) * 256 + c] : Wv[(r - 512) * 256 + c];
        d_Wq_h[idx] = __float2half(w);
    }
    if (idx < 1024)
        d_ball[idx] = (idx < 256) ? bq[idx] : (idx < 512) ? bk[idx - 256] : bv[idx - 512];
    if (idx < 256) {
        float s = gamma[idx] * rsqrtf(var[idx] + 1e-5f);
        d_s[idx] = s;
        d_t[idx] = (bf[idx] - mean[idx]) * s + beta[idx];
    }
}

// ---------------- convert x -> xT fp16 (transpose) -----------------------------
__global__ __launch_bounds__(256) void k_convx(const float* __restrict__ x) {
    __shared__ float t[64][33];
    int p0 = blockIdx.x * 32, c0 = blockIdx.y * 64, b = blockIdx.z;
    const float* src = x + ((size_t)b * 256 + c0) * HW + p0;
    int tid = threadIdx.x;
#pragma unroll
    for (int j = 0; j < 8; j++) {
        int idx = tid + j * 256;
        int cc = idx >> 5, pp = idx & 31;
        t[cc][pp] = src[(size_t)cc * HW + pp];
    }
    __syncthreads();
    __half2* oh = (__half2*)d_xT_h;
#pragma unroll
    for (int j = 0; j < 4; j++) {
        int idx = tid + j * 256;
        int p = idx >> 5, pr = idx & 31;
        oh[((size_t)b * HW + p0 + p) * 128 + (c0 >> 1) + pr] =
            __floats2half2_rn(t[pr * 2][p], t[pr * 2 + 1][p]);
    }
}

// ---------------- mma.sync GEMM (fp16 single-term) -----------------------------
// MODE 0: qkv = Wqkv @ x^T  -> writes d_qkvT (fp16, transposed) + partial ssq
// MODE 1: out = Wf2 @ z^T   -> B operand (z = gate*invq*q) folded in loader
// Block 128x128, 8 warps (2x4), warp tile 64x32, K-chunk 32, 2-stage cp.async,
// 2 CTAs/SM for cross-CTA latency hiding.
#define PITCH 80
#define TILE_BYTES (128 * PITCH)
#define SM_TILE(s, t) (((s) * 2 + (t)) * TILE_BYTES)
#define SMEM_SZ0 69632
#define SMEM_SZ1 40960

template <int MODE>
__global__ __launch_bounds__(256, 2) void k_mma(float* __restrict__ CoutExt) {
    extern __shared__ char smem[];
    uint32_t sb = smem_u32(smem);
    const int tid = threadIdx.x;
    const int lane = tid & 31;
    const int wid = tid >> 5;
    const int wm = wid >> 2, wn = wid & 3;
    const int m0w = wm * 64, n0w = wn * 32;
    const int b = blockIdx.z;
    const int nbase = blockIdx.x * 128;
    const int mbase = blockIdx.y * 128;

    const __half* Ah = (MODE == 0) ? d_Wq_h + (size_t)mbase * 256
                                   : d_W2_h + (size_t)b * 65536 + (size_t)mbase * 256;
    const __half* Bh = d_xT_h + (size_t)b * HW * 256 + (size_t)nbase * 256;

    const __half* bases2[2] = {Ah, Bh};

    auto load2 = [&](int kc, int s) {
#pragma unroll
        for (int j = 0; j < 4; j++) {
            int g = tid + j * 256;
            int t = g >> 9, w = g & 511;
            int r = w >> 2, c = w & 3;
            const char* src = (const char*)bases2[t] + ((size_t)r * 256 + kc * 32 + c * 8) * 2;
            cp16(sb + SM_TILE(s, t) + r * PITCH + c * 16, src);
        }
        CP_COMMIT();
    };
    auto loadA = [&](int kc, int s) {
#pragma unroll
        for (int j = 0; j < 2; j++) {
            int g = tid + j * 256;
            int r = g >> 2, c = g & 3;
            const char* src = (const char*)Ah + ((size_t)r * 256 + kc * 32 + c * 8) * 2;
            cp16(sb + SM_TILE(s, 0) + r * PITCH + c * 16, src);
        }
        CP_COMMIT();
    };

    float fpx[2];
    float breg[2][8];
    auto ldB = [&](int kc) {
#pragma unroll
        for (int j = 0; j < 2; j++) {
            int idx = tid + j * 256;
            int r = idx >> 2, c8 = idx & 3;
            int p = nbase + r;
            float f = fpx[j] * d_gate[(size_t)(b * 8 + kc) * HW + p];
            const __half2* src = (const __half2*)&d_qkvT[((size_t)b * HW + p) * 1024 + kc * 32 + c8 * 8];
#pragma unroll
            for (int u = 0; u < 4; u++) {
                float2 v = __half22float2(src[u]);
                breg[j][u * 2]     = v.x * f;
                breg[j][u * 2 + 1] = v.y * f;
            }
        }
    };
    auto stB = [&](int s) {
#pragma unroll
        for (int j = 0; j < 2; j++) {
            int idx = tid + j * 256;
            int r = idx >> 2, c8 = idx & 3;
            __half2* dst = (__half2*)(smem + SM_TILE(s, 1) + r * PITCH + c8 * 16);
#pragma unroll
            for (int u = 0; u < 4; u++)
                dst[u] = __floats2half2_rn(breg[j][u * 2], breg[j][u * 2 + 1]);
        }
    };

    float acc[4][4][4] = {};
    const int a_row = lane & 15;
    const int a_colh = (lane >> 4) << 3;
    const int b_row = (lane & 7) + ((lane >> 4) << 3);
    const int b_colh = ((lane >> 3) & 1) << 3;

    if (MODE == 0) {
        load2(0, 0); load2(1, 1);
    } else {
#pragma unroll
        for (int j = 0; j < 2; j++)
            fpx[j] = d_invq[b * HW + nbase + ((tid + j * 256) >> 2)];
        loadA(0, 0); loadA(1, 1);
        ldB(0);
    }

#pragma unroll
    for (int i = 0; i < 8; i++) {
        const int s = i & 1;
        if (MODE == 1) stB(s);
        if (i < 6) asm volatile("cp.async.wait_group 1;" ::: "memory");
        else       asm volatile("cp.async.wait_group 0;" ::: "memory");
        __syncthreads();
        if (MODE == 1 && i + 1 < 8) ldB(i + 1);

        const uint32_t tAh = sb + SM_TILE(s, 0);
        const uint32_t tBh = sb + SM_TILE(s, 1);
#pragma unroll
        for (int ks = 0; ks < 2; ks++) {
            const int kh = ks * 16;
            uint32_t aH[4][4], bH[4][2];
#pragma unroll
            for (int mt = 0; mt < 4; mt++) {
                uint32_t off = (uint32_t)(m0w + mt * 16 + a_row) * PITCH + (kh + a_colh) * 2;
                ldsm4(aH[mt], tAh + off);
            }
#pragma unroll
            for (int bt = 0; bt < 2; bt++) {
                uint32_t off = (uint32_t)(n0w + bt * 16 + b_row) * PITCH + (kh + b_colh) * 2;
                uint32_t rh[4];
                ldsm4(rh, tBh + off);
                bH[bt * 2][0] = rh[0]; bH[bt * 2][1] = rh[1];
                bH[bt * 2 + 1][0] = rh[2]; bH[bt * 2 + 1][1] = rh[3];
            }
#pragma unroll
            for (int mt = 0; mt < 4; mt++)
#pragma unroll
                for (int nt = 0; nt < 4; nt++)
                    mma16816(acc[mt][nt], aH[mt], bH[nt][0], bH[nt][1]);
        }
        __syncthreads();
        if (i + 2 < 8) { if (MODE == 0) load2(i + 2, s); else loadA(i + 2, s); }
    }

    if (MODE == 0) {
        float* sT = (float*)smem;
        __syncthreads();
#pragma unroll
        for (int mt = 0; mt < 4; mt++) {
            int rr0 = m0w + mt * 16 + (lane >> 2);
            int rr1 = rr0 + 8;
            float b0 = d_ball[mbase + rr0], b1 = d_ball[mbase + rr1];
#pragma unroll
            for (int nt = 0; nt < 4; nt++) {
                int cc = n0w + nt * 8 + (lane & 3) * 2;
                sT[(cc) * 132 + rr0]     = acc[mt][nt][0] + b0;
                sT[(cc + 1) * 132 + rr0] = acc[mt][nt][1] + b0;
                sT[(cc) * 132 + rr1]     = acc[mt][nt][2] + b1;
                sT[(cc + 1) * 132 + rr1] = acc[mt][nt][3] + b1;
            }
        }
        __syncthreads();
#pragma unroll
        for (int j = 0; j < 16; j++) {
            int idx = tid + j * 256;
            int px = idx >> 5, c4 = idx & 31;
            float4 v = *(float4*)&sT[px * 132 + c4 * 4];
            __half2* dst = (__half2*)&d_qkvT[((size_t)b * HW + nbase + px) * 1024 + mbase + c4 * 4];
            dst[0] = __floats2half2_rn(v.x, v.y);
            dst[1] = __floats2half2_rn(v.z, v.w);
        }
        if (mbase < 512 && tid < 128) {
            int px = tid;
            float s = 0.f;
#pragma unroll
            for (int c4 = 0; c4 < 32; c4++) {
                float4 v = *(float4*)&sT[px * 132 + c4 * 4];
                s += v.x * v.x + v.y * v.y + v.z * v.z + v.w * v.w;
            }
            d_ssqp[(size_t)(mbase >> 7) * (B_ * HW) + b * HW + nbase + px] = s;
        }
    } else {
        float* Cg = CoutExt + (size_t)b * 256 * HW;
#pragma unroll
        for (int mt = 0; mt < 4; mt++) {
            int r0 = mbase + m0w + mt * 16 + (lane >> 2);
            int r1 = r0 + 8;
            float sc0 = d_s[r0], t0 = d_t[r0], sc1 = d_s[r1], t1 = d_t[r1];
#pragma unroll
            for (int nt = 0; nt < 4; nt++) {
                int c = nbase + n0w + nt * 8 + (lane & 3) * 2;
                float2 o0, o1;
                o0.x = fmaxf(acc[mt][nt][0] * sc0 + t0, 0.f);
                o0.y = fmaxf(acc[mt][nt][1] * sc0 + t0, 0.f);
                o1.x = fmaxf(acc[mt][nt][2] * sc1 + t1, 0.f);
                o1.y = fmaxf(acc[mt][nt][3] * sc1 + t1, 0.f);
                *(float2*)&Cg[(size_t)r0 * HW + c] = o0;
                *(float2*)&Cg[(size_t)r1 * HW + c] = o1;
            }
        }
    }
}

// ---------------- K2s: finish pixelnorm factors --------------------------------
__global__ void k2s() {
    int i = blockIdx.x * blockDim.x + threadIdx.x;
    float sq = d_ssqp[i] + d_ssqp[B_ * HW + i];
    float sk = d_ssqp[2 * B_ * HW + i] + d_ssqp[3 * B_ * HW + i];
    d_invq[i] = rsqrtf(sq * (1.f / 256.f) + 1e-8f);
    d_invk[i] = rsqrtf(sk * (1.f / 256.f) + 1e-8f);
}

// ---------------- K3a: per-head partial kv = (k*invk) @ v^T --------------------
// Square warp tiles: 8 warps as 2(ch)x4(C); warp tile 16ch x 16C; thread 2ch x 4C.
// Distinct LDS lanes per warp per pixel: 16(k) + 16(v) = 32 (vs 68 before).
__global__ __launch_bounds__(256) void k3a_kv() {
    int head = blockIdx.y, split = blockIdx.x;
    int b = head >> 3, h = head & 7;

    __shared__ float ks[128][32];
    __shared__ float vs[128][64];

    int tid = threadIdx.x;
    int lane = tid & 31;
    int wid = tid >> 5;
    int wm = wid >> 2, wn = wid & 3;
    int ch0 = wm * 16 + (lane & 7) * 2;
    int C0  = wn * 16 + (lane >> 3) * 4;
    float acc[2][4] = {};

    for (int it = 0; it < 4; it++) {
        int pb = split * 512 + it * 128;
#pragma unroll
        for (int j = 0; j < 2; j++) {
            int idx = tid + j * 256;
            int r = idx >> 2, c8 = idx & 3;
            int p = pb + r;
            float iv = d_invk[b * HW + p];
            const __half2* src = (const __half2*)&d_qkvT[((size_t)b * HW + p) * 1024 + 256 + h * 32 + c8 * 8];
#pragma unroll
            for (int u = 0; u < 4; u++) {
                float2 v = __half22float2(src[u]);
                ks[r][c8 * 8 + u * 2]     = v.x * iv;
                ks[r][c8 * 8 + u * 2 + 1] = v.y * iv;
            }
        }
#pragma unroll
        for (int j = 0; j < 4; j++) {
            int idx = tid + j * 256;
            int r = idx >> 3, c8 = idx & 7;
            int p = pb + r;
            const __half2* src = (const __half2*)&d_qkvT[((size_t)b * HW + p) * 1024 + 512 + h * 64 + c8 * 8];
#pragma unroll
            for (int u = 0; u < 4; u++) {
                float2 v = __half22float2(src[u]);
                vs[r][c8 * 8 + u * 2]     = v.x;
                vs[r][c8 * 8 + u * 2 + 1] = v.y;
            }
        }
        __syncthreads();
#pragma unroll 4
        for (int p = 0; p < 128; p++) {
            float4 v4 = *(const float4*)&vs[p][C0];
            float2 kk = *(const float2*)&ks[p][ch0];
            acc[0][0] += kk.x * v4.x; acc[0][1] += kk.x * v4.y;
            acc[0][2] += kk.x * v4.z; acc[0][3] += kk.x * v4.w;
            acc[1][0] += kk.y * v4.x; acc[1][1] += kk.y * v4.y;
            acc[1][2] += kk.y * v4.z; acc[1][3] += kk.y * v4.w;
        }
        __syncthreads();
    }
    float* out = d_kvpart + ((size_t)head * 8 + split) * 2048;
#pragma unroll
    for (int i = 0; i < 2; i++)
#pragma unroll
        for (int j = 0; j < 4; j++)
            out[(ch0 + i) * 64 + C0 + j] = acc[i][j];
}

// ---------------- K3b: reduce kv, pixelnorm, m, Wf2 (writes fp16) --------------
__global__ __launch_bounds__(256) void k3b_kvnorm(const float* __restrict__ Wf) {
    int head = blockIdx.x;
    int b = head >> 3, h = head & 7;
    __shared__ float skv[2048];
    __shared__ float nrm[64];
    int tid = threadIdx.x;
#pragma unroll
    for (int s = 0; s < 8; s++) {
        int idx = tid + s * 256;
        float sum = 0.f;
#pragma unroll
        for (int sp = 0; sp < 8; sp++)
            sum += d_kvpart[(size_t)(head * 8 + sp) * 2048 + idx];
        skv[idx] = sum;
    }
    __syncthreads();
    if (tid < 64) {
        float s = 0.f;
#pragma unroll
        for (int c = 0; c < 32; c++) { float v = skv[c * 64 + tid]; s += v * v; }
        nrm[tid] = rsqrtf(s * (1.f / 32.f) + 1e-8f);
    }
    __syncthreads();
#pragma unroll
    for (int s = 0; s < 8; s++) {
        int idx = tid + s * 256;
        skv[idx] *= nrm[idx & 63];
    }
    __syncthreads();
    if (tid < 32) {
        float s = 0.f;
#pragma unroll
        for (int C = 32; C < 64; C++) s += skv[tid * 64 + C];
        d_m[head * 32 + tid] = s * (1.f / 32.f);
    }
    int o = tid;
    float wf[32];
#pragma unroll
    for (int c2 = 0; c2 < 32; c2++) wf[c2] = Wf[o * 256 + h * 32 + c2];
    size_t ob = (size_t)b * 65536 + o * 256 + h * 32;
    for (int c = 0; c < 32; c++) {
        float s = 0.f;
#pragma unroll
        for (int c2 = 0; c2 < 32; c2++) s += wf[c2] * skv[c * 64 + c2];
        d_W2_h[ob + c] = __float2half(s);
    }
}

// ---------------- K4: spatial softmax gate (fp16 q) ----------------------------
__global__ __launch_bounds__(1024) void k4_gate() {
    int head = blockIdx.x;
    int b = head >> 3, h = head & 7;
    __shared__ float sm[32];
    __shared__ float red[1024];
    int tid = threadIdx.x;
    if (tid < 32) sm[tid] = d_m[head * 32 + tid];
    __syncthreads();

    float z[4];
    float lmax = -1e30f;
#pragma unroll
    for (int i = 0; i < 4; i++) {
        int p = tid + i * 1024;
        const __half2* row = (const __half2*)&d_qkvT[((size_t)b * HW + p) * 1024 + h * 32];
        float s = 0.f;
#pragma unroll
        for (int c2 = 0; c2 < 16; c2++) {
            float2 q = __half22float2(row[c2]);
            s += q.x * sm[c2 * 2] + q.y * sm[c2 * 2 + 1];
        }
        z[i] = s * d_invq[b * HW + p] * (1.f / 64.f);
        lmax = fmaxf(lmax, z[i]);
    }
    red[tid] = lmax; __syncthreads();
    for (int st = 512; st > 0; st >>= 1) {
        if (tid < st) red[tid] = fmaxf(red[tid], red[tid + st]);
        __syncthreads();
    }
    float gmax = red[0]; __syncthreads();
    float lsum = 0.f;
#pragma unroll
    for (int i = 0; i < 4; i++) { z[i] = __expf(z[i] - gmax); lsum += z[i]; }
    red[tid] = lsum; __syncthreads();
    for (int st = 512; st > 0; st >>= 1) {
        if (tid < st) red[tid] += red[tid + st];
        __syncthreads();
    }
    float inv = 1.f / red[0];
#pragma unroll
    for (int i = 0; i < 4; i++)
        d_gate[(size_t)head * HW + tid + i * 1024] = z[i] * inv;
}

// ---------------- launch --------------------------------------------------------
extern "C" void kernel_launch(void* const* d_in, const int* in_sizes, int n_in,
                              void* d_out, int out_size) {
    const float* x     = (const float*)d_in[0];
    const float* Wq    = (const float*)d_in[1];
    const float* bq    = (const float*)d_in[2];
    const float* Wk    = (const float*)d_in[3];
    const float* bk    = (const float*)d_in[4];
    const float* Wv    = (const float*)d_in[5];
    const float* bv    = (const float*)d_in[6];
    const float* Wf    = (const float*)d_in[7];
    const float* bf    = (const float*)d_in[8];
    const float* gamma = (const float*)d_in[9];
    const float* beta  = (const float*)d_in[10];
    const float* mean  = (const float*)d_in[11];
    const float* var   = (const float*)d_in[12];
    float* out = (float*)d_out;

    static bool attr_set = false;
    if (!attr_set) {
        cudaFuncSetAttribute(k_mma<0>, cudaFuncAttributeMaxDynamicSharedMemorySize, SMEM_SZ0);
        cudaFuncSetAttribute(k_mma<1>, cudaFuncAttributeMaxDynamicSharedMemorySize, SMEM_SZ1);
        attr_set = true;
    }

    k0_prep<<<(1024 * 256 + 255) / 256, 256>>>(Wq, bq, Wk, bk, Wv, bv, bf, gamma, beta, mean, var);
    k_convx<<<dim3(128, 4, B_), 256>>>(x);
    k_mma<0><<<dim3(32, 8, B_), 256, SMEM_SZ0>>>(nullptr);
    k2s<<<256, 128>>>();
    k3a_kv<<<dim3(8, 64), 256>>>();
    k3b_kvnorm<<<64, 256>>>(Wf);
    k4_gate<<<64, 1024>>>();
    k_mma<1><<<dim3(32, 2, B_), 256, SMEM_SZ1>>>(out);
}

// round 10
// speedup vs baseline: 1.6273x; 1.0654x over previous
#include <cuda_runtime.h>
#include <cuda_fp16.h>
#include <cstdint>

#define HW 4096
#define B_ 8

// ---------------- scratch -----------------------------------------------------
__device__ __half d_qkvT[(size_t)B_ * HW * 1024];  // pixel-major fp16: [b][p][ch]
__device__ float d_ssqp[4 * B_ * HW];              // partial ssq tiles q0,q1,k0,k1
__device__ float d_invq[B_ * HW];
__device__ float d_invk[B_ * HW];
__device__ float d_kvpart[64 * 8 * 2048];
__device__ float d_m[64 * 32];
__device__ float d_gate[64 * HW];
__device__ float d_ball[1024];
__device__ float d_s[256];
__device__ float d_t[256];
__device__ __half d_Wq_h[1024 * 256];
__device__ __half d_xT_h[(size_t)B_ * HW * 256];
__device__ __half d_W2_h[B_ * 256 * 256];

// ---------------- helpers -------------------------------------------------------
__device__ __forceinline__ uint32_t smem_u32(const void* p) {
    uint32_t a;
    asm("{ .reg .u64 t; cvta.to.shared.u64 t, %1; cvt.u32.u64 %0, t; }" : "=r"(a) : "l"(p));
    return a;
}
__device__ __forceinline__ void cp16(uint32_t dst, const void* src) {
    asm volatile("cp.async.cg.shared.global [%0], [%1], 16;" :: "r"(dst), "l"(src));
}
#define CP_COMMIT() asm volatile("cp.async.commit_group;" ::: "memory")

__device__ __forceinline__ void ldsm4(uint32_t* r, uint32_t addr) {
    asm volatile("ldmatrix.sync.aligned.m8n8.x4.shared.b16 {%0,%1,%2,%3}, [%4];"
        : "=r"(r[0]), "=r"(r[1]), "=r"(r[2]), "=r"(r[3]) : "r"(addr));
}
__device__ __forceinline__ void mma16816(float* d, const uint32_t* a, uint32_t b0, uint32_t b1) {
    asm volatile("mma.sync.aligned.m16n8k16.row.col.f32.f16.f16.f32 "
        "{%0,%1,%2,%3}, {%4,%5,%6,%7}, {%8,%9}, {%0,%1,%2,%3};"
        : "+f"(d[0]), "+f"(d[1]), "+f"(d[2]), "+f"(d[3])
        : "r"(a[0]), "r"(a[1]), "r"(a[2]), "r"(a[3]), "r"(b0), "r"(b1));
}

// ---------------- K0: pack weights fp16, biases, BN fold -----------------------
__global__ void k0_prep(const float* __restrict__ Wq, const float* __restrict__ bq,
                        const float* __restrict__ Wk, const float* __restrict__ bk,
                        const float* __restrict__ Wv, const float* __restrict__ bv,
                        const float* __restrict__ bf,
                        const float* __restrict__ gamma, const float* __restrict__ beta,
                        const float* __restrict__ mean,  const float* __restrict__ var) {
    int idx = blockIdx.x * blockDim.x + threadIdx.x;
    if (idx < 1024 * 256) {
        int r = idx >> 8, c = idx & 255;
        float w = (r < 256) ? Wq[r * 256 + c] : (r < 512) ? Wk[(r - 256) * 256 + c] : Wv[(r - 512) * 256 + c];
        d_Wq_h[idx] = __float2half(w);
    }
    if (idx < 1024)
        d_ball[idx] = (idx < 256) ? bq[idx] : (idx < 512) ? bk[idx - 256] : bv[idx - 512];
    if (idx < 256) {
        float s = gamma[idx] * rsqrtf(var[idx] + 1e-5f);
        d_s[idx] = s;
        d_t[idx] = (bf[idx] - mean[idx]) * s + beta[idx];
    }
}

// ---------------- convert x -> xT fp16 (transpose) -----------------------------
__global__ __launch_bounds__(256) void k_convx(const float* __restrict__ x) {
    __shared__ float t[64][33];
    int p0 = blockIdx.x * 32, c0 = blockIdx.y * 64, b = blockIdx.z;
    const float* src = x + ((size_t)b * 256 + c0) * HW + p0;
    int tid = threadIdx.x;
#pragma unroll
    for (int j = 0; j < 8; j++) {
        int idx = tid + j * 256;
        int cc = idx >> 5, pp = idx & 31;
        t[cc][pp] = src[(size_t)cc * HW + pp];
    }
    __syncthreads();
    __half2* oh = (__half2*)d_xT_h;
#pragma unroll
    for (int j = 0; j < 4; j++) {
        int idx = tid + j * 256;
        int p = idx >> 5, pr = idx & 31;
        oh[((size_t)b * HW + p0 + p) * 128 + (c0 >> 1) + pr] =
            __floats2half2_rn(t[pr * 2][p], t[pr * 2 + 1][p]);
    }
}

// ---------------- mma.sync GEMM (fp16 single-term) -----------------------------
#define PITCH 80
#define TILE_BYTES (128 * PITCH)
#define SM_TILE(s, t) (((s) * 2 + (t)) * TILE_BYTES)
#define SMEM_SZ0 69632
#define SMEM_SZ1 40960

template <int MODE>
__global__ __launch_bounds__(256, 2) void k_mma(float* __restrict__ CoutExt) {
    extern __shared__ char smem[];
    uint32_t sb = smem_u32(smem);
    const int tid = threadIdx.x;
    const int lane = tid & 31;
    const int wid = tid >> 5;
    const int wm = wid >> 2, wn = wid & 3;
    const int m0w = wm * 64, n0w = wn * 32;
    const int b = blockIdx.z;
    const int nbase = blockIdx.x * 128;
    const int mbase = blockIdx.y * 128;

    const __half* Ah = (MODE == 0) ? d_Wq_h + (size_t)mbase * 256
                                   : d_W2_h + (size_t)b * 65536 + (size_t)mbase * 256;
    const __half* Bh = d_xT_h + (size_t)b * HW * 256 + (size_t)nbase * 256;

    const __half* bases2[2] = {Ah, Bh};

    auto load2 = [&](int kc, int s) {
#pragma unroll
        for (int j = 0; j < 4; j++) {
            int g = tid + j * 256;
            int t = g >> 9, w = g & 511;
            int r = w >> 2, c = w & 3;
            const char* src = (const char*)bases2[t] + ((size_t)r * 256 + kc * 32 + c * 8) * 2;
            cp16(sb + SM_TILE(s, t) + r * PITCH + c * 16, src);
        }
        CP_COMMIT();
    };
    auto loadA = [&](int kc, int s) {
#pragma unroll
        for (int j = 0; j < 2; j++) {
            int g = tid + j * 256;
            int r = g >> 2, c = g & 3;
            const char* src = (const char*)Ah + ((size_t)r * 256 + kc * 32 + c * 8) * 2;
            cp16(sb + SM_TILE(s, 0) + r * PITCH + c * 16, src);
        }
        CP_COMMIT();
    };

    float fpx[2];
    float breg[2][8];
    auto ldB = [&](int kc) {
#pragma unroll
        for (int j = 0; j < 2; j++) {
            int idx = tid + j * 256;
            int r = idx >> 2, c8 = idx & 3;
            int p = nbase + r;
            float f = fpx[j] * d_gate[(size_t)(b * 8 + kc) * HW + p];
            const __half2* src = (const __half2*)&d_qkvT[((size_t)b * HW + p) * 1024 + kc * 32 + c8 * 8];
#pragma unroll
            for (int u = 0; u < 4; u++) {
                float2 v = __half22float2(src[u]);
                breg[j][u * 2]     = v.x * f;
                breg[j][u * 2 + 1] = v.y * f;
            }
        }
    };
    auto stB = [&](int s) {
#pragma unroll
        for (int j = 0; j < 2; j++) {
            int idx = tid + j * 256;
            int r = idx >> 2, c8 = idx & 3;
            __half2* dst = (__half2*)(smem + SM_TILE(s, 1) + r * PITCH + c8 * 16);
#pragma unroll
            for (int u = 0; u < 4; u++)
                dst[u] = __floats2half2_rn(breg[j][u * 2], breg[j][u * 2 + 1]);
        }
    };

    float acc[4][4][4] = {};
    const int a_row = lane & 15;
    const int a_colh = (lane >> 4) << 3;
    const int b_row = (lane & 7) + ((lane >> 4) << 3);
    const int b_colh = ((lane >> 3) & 1) << 3;

    if (MODE == 0) {
        load2(0, 0); load2(1, 1);
    } else {
#pragma unroll
        for (int j = 0; j < 2; j++)
            fpx[j] = d_invq[b * HW + nbase + ((tid + j * 256) >> 2)];
        loadA(0, 0); loadA(1, 1);
        ldB(0);
    }

#pragma unroll
    for (int i = 0; i < 8; i++) {
        const int s = i & 1;
        if (MODE == 1) stB(s);
        if (i < 6) asm volatile("cp.async.wait_group 1;" ::: "memory");
        else       asm volatile("cp.async.wait_group 0;" ::: "memory");
        __syncthreads();
        if (MODE == 1 && i + 1 < 8) ldB(i + 1);

        const uint32_t tAh = sb + SM_TILE(s, 0);
        const uint32_t tBh = sb + SM_TILE(s, 1);
#pragma unroll
        for (int ks = 0; ks < 2; ks++) {
            const int kh = ks * 16;
            uint32_t aH[4][4], bH[4][2];
#pragma unroll
            for (int mt = 0; mt < 4; mt++) {
                uint32_t off = (uint32_t)(m0w + mt * 16 + a_row) * PITCH + (kh + a_colh) * 2;
                ldsm4(aH[mt], tAh + off);
            }
#pragma unroll
            for (int bt = 0; bt < 2; bt++) {
                uint32_t off = (uint32_t)(n0w + bt * 16 + b_row) * PITCH + (kh + b_colh) * 2;
                uint32_t rh[4];
                ldsm4(rh, tBh + off);
                bH[bt * 2][0] = rh[0]; bH[bt * 2][1] = rh[1];
                bH[bt * 2 + 1][0] = rh[2]; bH[bt * 2 + 1][1] = rh[3];
            }
#pragma unroll
            for (int mt = 0; mt < 4; mt++)
#pragma unroll
                for (int nt = 0; nt < 4; nt++)
                    mma16816(acc[mt][nt], aH[mt], bH[nt][0], bH[nt][1]);
        }
        __syncthreads();
        if (i + 2 < 8) { if (MODE == 0) load2(i + 2, s); else loadA(i + 2, s); }
    }

    if (MODE == 0) {
        float* sT = (float*)smem;
        __syncthreads();
#pragma unroll
        for (int mt = 0; mt < 4; mt++) {
            int rr0 = m0w + mt * 16 + (lane >> 2);
            int rr1 = rr0 + 8;
            float b0 = d_ball[mbase + rr0], b1 = d_ball[mbase + rr1];
#pragma unroll
            for (int nt = 0; nt < 4; nt++) {
                int cc = n0w + nt * 8 + (lane & 3) * 2;
                sT[(cc) * 132 + rr0]     = acc[mt][nt][0] + b0;
                sT[(cc + 1) * 132 + rr0] = acc[mt][nt][1] + b0;
                sT[(cc) * 132 + rr1]     = acc[mt][nt][2] + b1;
                sT[(cc + 1) * 132 + rr1] = acc[mt][nt][3] + b1;
            }
        }
        __syncthreads();
#pragma unroll
        for (int j = 0; j < 16; j++) {
            int idx = tid + j * 256;
            int px = idx >> 5, c4 = idx & 31;
            float4 v = *(float4*)&sT[px * 132 + c4 * 4];
            __half2* dst = (__half2*)&d_qkvT[((size_t)b * HW + nbase + px) * 1024 + mbase + c4 * 4];
            dst[0] = __floats2half2_rn(v.x, v.y);
            dst[1] = __floats2half2_rn(v.z, v.w);
        }
        if (mbase < 512 && tid < 128) {
            int px = tid;
            float s = 0.f;
#pragma unroll
            for (int c4 = 0; c4 < 32; c4++) {
                float4 v = *(float4*)&sT[px * 132 + c4 * 4];
                s += v.x * v.x + v.y * v.y + v.z * v.z + v.w * v.w;
            }
            d_ssqp[(size_t)(mbase >> 7) * (B_ * HW) + b * HW + nbase + px] = s;
        }
    } else {
        float* Cg = CoutExt + (size_t)b * 256 * HW;
#pragma unroll
        for (int mt = 0; mt < 4; mt++) {
            int r0 = mbase + m0w + mt * 16 + (lane >> 2);
            int r1 = r0 + 8;
            float sc0 = d_s[r0], t0 = d_t[r0], sc1 = d_s[r1], t1 = d_t[r1];
#pragma unroll
            for (int nt = 0; nt < 4; nt++) {
                int c = nbase + n0w + nt * 8 + (lane & 3) * 2;
                float2 o0, o1;
                o0.x = fmaxf(acc[mt][nt][0] * sc0 + t0, 0.f);
                o0.y = fmaxf(acc[mt][nt][1] * sc0 + t0, 0.f);
                o1.x = fmaxf(acc[mt][nt][2] * sc1 + t1, 0.f);
                o1.y = fmaxf(acc[mt][nt][3] * sc1 + t1, 0.f);
                *(float2*)&Cg[(size_t)r0 * HW + c] = o0;
                *(float2*)&Cg[(size_t)r1 * HW + c] = o1;
            }
        }
    }
}

// ---------------- K2s: finish pixelnorm factors --------------------------------
__global__ void k2s() {
    int i = blockIdx.x * blockDim.x + threadIdx.x;
    float sq = d_ssqp[i] + d_ssqp[B_ * HW + i];
    float sk = d_ssqp[2 * B_ * HW + i] + d_ssqp[3 * B_ * HW + i];
    d_invq[i] = rsqrtf(sq * (1.f / 256.f) + 1e-8f);
    d_invk[i] = rsqrtf(sk * (1.f / 256.f) + 1e-8f);
}

// ---------------- K3a: per-head partial kv = k @ (v*invk)^T via mma.sync -------
// Output 32x64 per (head,split), K = 512 pixels in 8 chunks of 64.
// Stage k (raw fp16) and v*invk (fp16) transposed to [ch][px], PITCH 144B.
// Fragment recipe identical to k_mma (A row-major [m][K], B col-major [n][K]).
#define KP 144
__global__ __launch_bounds__(256) void k3a_kv() {
    __shared__ char smk[32 * KP];
    __shared__ char smv[64 * KP];
    int head = blockIdx.y, split = blockIdx.x;
    int b = head >> 3, h = head & 7;
    int tid = threadIdx.x;
    int lane = tid & 31, wid = tid >> 5;
    int wm = wid >> 2, wn = wid & 3;          // warp grid 2(m) x 4(n)

    const int a_row = lane & 15;
    const int a_colh = (lane >> 4) << 3;
    const int b_row = (lane & 7) + ((lane >> 4) << 3);
    const int b_colh = ((lane >> 3) & 1) << 3;
    const uint32_t kbase = smem_u32(smk);
    const uint32_t vbase = smem_u32(smv);

    float acc[2][4] = {};

    for (int it = 0; it < 8; it++) {
        int pb = split * 512 + it * 64;
        // stage k: 64 px x 32 ch, one 16B read per thread, transposed store
        {
            int p = tid >> 2, c8 = tid & 3;
            const __half2* src = (const __half2*)&d_qkvT[((size_t)b * HW + pb + p) * 1024 + 256 + h * 32 + c8 * 8];
#pragma unroll
            for (int u = 0; u < 4; u++) {
                __half2 v = src[u];
                int ch = c8 * 8 + u * 2;
                *(__half*)(smk + ch * KP + p * 2)       = __low2half(v);
                *(__half*)(smk + (ch + 1) * KP + p * 2) = __high2half(v);
            }
        }
        // stage v * invk: 64 px x 64 ch
#pragma unroll
        for (int j = 0; j < 2; j++) {
            int idx = tid + j * 256;
            int p = idx >> 3, c8 = idx & 7;
            float iv = d_invk[b * HW + pb + p];
            const __half2* src = (const __half2*)&d_qkvT[((size_t)b * HW + pb + p) * 1024 + 512 + h * 64 + c8 * 8];
#pragma unroll
            for (int u = 0; u < 4; u++) {
                float2 v = __half22float2(src[u]);
                int ch = c8 * 8 + u * 2;
                *(__half*)(smv + ch * KP + p * 2)       = __float2half(v.x * iv);
                *(__half*)(smv + (ch + 1) * KP + p * 2) = __float2half(v.y * iv);
            }
        }
        __syncthreads();
#pragma unroll
        for (int kc = 0; kc < 4; kc++) {
            int kh = kc * 16;
            uint32_t aH[4], bF[4];
            ldsm4(aH, kbase + (uint32_t)(wm * 16 + a_row) * KP + (kh + a_colh) * 2);
            ldsm4(bF, vbase + (uint32_t)(wn * 16 + b_row) * KP + (kh + b_colh) * 2);
            mma16816(acc[0], aH, bF[0], bF[1]);
            mma16816(acc[1], aH, bF[2], bF[3]);
        }
        __syncthreads();
    }

    float* out = d_kvpart + ((size_t)head * 8 + split) * 2048;
    int c0 = wm * 16 + (lane >> 2);
#pragma unroll
    for (int nt = 0; nt < 2; nt++) {
        int C = wn * 16 + nt * 8 + (lane & 3) * 2;
        out[c0 * 64 + C]           = acc[nt][0];
        out[c0 * 64 + C + 1]       = acc[nt][1];
        out[(c0 + 8) * 64 + C]     = acc[nt][2];
        out[(c0 + 8) * 64 + C + 1] = acc[nt][3];
    }
}

// ---------------- K3b: reduce kv, pixelnorm, m, Wf2 (writes fp16) --------------
__global__ __launch_bounds__(256) void k3b_kvnorm(const float* __restrict__ Wf) {
    int head = blockIdx.x;
    int b = head >> 3, h = head & 7;
    __shared__ float skv[2048];
    __shared__ float nrm[64];
    int tid = threadIdx.x;
#pragma unroll
    for (int s = 0; s < 8; s++) {
        int idx = tid + s * 256;
        float sum = 0.f;
#pragma unroll
        for (int sp = 0; sp < 8; sp++)
            sum += d_kvpart[(size_t)(head * 8 + sp) * 2048 + idx];
        skv[idx] = sum;
    }
    __syncthreads();
    if (tid < 64) {
        float s = 0.f;
#pragma unroll
        for (int c = 0; c < 32; c++) { float v = skv[c * 64 + tid]; s += v * v; }
        nrm[tid] = rsqrtf(s * (1.f / 32.f) + 1e-8f);
    }
    __syncthreads();
#pragma unroll
    for (int s = 0; s < 8; s++) {
        int idx = tid + s * 256;
        skv[idx] *= nrm[idx & 63];
    }
    __syncthreads();
    if (tid < 32) {
        float s = 0.f;
#pragma unroll
        for (int C = 32; C < 64; C++) s += skv[tid * 64 + C];
        d_m[head * 32 + tid] = s * (1.f / 32.f);
    }
    int o = tid;
    float wf[32];
#pragma unroll
    for (int c2 = 0; c2 < 32; c2++) wf[c2] = Wf[o * 256 + h * 32 + c2];
    size_t ob = (size_t)b * 65536 + o * 256 + h * 32;
    for (int c = 0; c < 32; c++) {
        float s = 0.f;
#pragma unroll
        for (int c2 = 0; c2 < 32; c2++) s += wf[c2] * skv[c * 64 + c2];
        d_W2_h[ob + c] = __float2half(s);
    }
}

// ---------------- K4: spatial softmax gate (shuffle reductions) ----------------
__global__ __launch_bounds__(1024) void k4_gate() {
    int head = blockIdx.x;
    int b = head >> 3, h = head & 7;
    __shared__ float sm[32];
    __shared__ float wred[32];
    __shared__ float bmax, bsum;
    int tid = threadIdx.x;
    int lane = tid & 31, wid = tid >> 5;
    if (tid < 32) sm[tid] = d_m[head * 32 + tid];
    __syncthreads();

    float z[4];
    float lmax = -1e30f;
#pragma unroll
    for (int i = 0; i < 4; i++) {
        int p = tid + i * 1024;
        const __half2* row = (const __half2*)&d_qkvT[((size_t)b * HW + p) * 1024 + h * 32];
        float s = 0.f;
#pragma unroll
        for (int c2 = 0; c2 < 16; c2++) {
            float2 q = __half22float2(row[c2]);
            s += q.x * sm[c2 * 2] + q.y * sm[c2 * 2 + 1];
        }
        z[i] = s * d_invq[b * HW + p] * (1.f / 64.f);
        lmax = fmaxf(lmax, z[i]);
    }
#pragma unroll
    for (int o = 16; o > 0; o >>= 1) lmax = fmaxf(lmax, __shfl_xor_sync(0xffffffffu, lmax, o));
    if (lane == 0) wred[wid] = lmax;
    __syncthreads();
    if (tid < 32) {
        float m = wred[tid];
#pragma unroll
        for (int o = 16; o > 0; o >>= 1) m = fmaxf(m, __shfl_xor_sync(0xffffffffu, m, o));
        if (tid == 0) bmax = m;
    }
    __syncthreads();
    float gmax = bmax;
    float lsum = 0.f;
#pragma unroll
    for (int i = 0; i < 4; i++) { z[i] = __expf(z[i] - gmax); lsum += z[i]; }
#pragma unroll
    for (int o = 16; o > 0; o >>= 1) lsum += __shfl_xor_sync(0xffffffffu, lsum, o);
    if (lane == 0) wred[wid] = lsum;
    __syncthreads();
    if (tid < 32) {
        float s = wred[tid];
#pragma unroll
        for (int o = 16; o > 0; o >>= 1) s += __shfl_xor_sync(0xffffffffu, s, o);
        if (tid == 0) bsum = s;
    }
    __syncthreads();
    float inv = 1.f / bsum;
#pragma unroll
    for (int i = 0; i < 4; i++)
        d_gate[(size_t)head * HW + tid + i * 1024] = z[i] * inv;
}

// ---------------- launch --------------------------------------------------------
extern "C" void kernel_launch(void* const* d_in, const int* in_sizes, int n_in,
                              void* d_out, int out_size) {
    const float* x     = (const float*)d_in[0];
    const float* Wq    = (const float*)d_in[1];
    const float* bq    = (const float*)d_in[2];
    const float* Wk    = (const float*)d_in[3];
    const float* bk    = (const float*)d_in[4];
    const float* Wv    = (const float*)d_in[5];
    const float* bv    = (const float*)d_in[6];
    const float* Wf    = (const float*)d_in[7];
    const float* bf    = (const float*)d_in[8];
    const float* gamma = (const float*)d_in[9];
    const float* beta  = (const float*)d_in[10];
    const float* mean  = (const float*)d_in[11];
    const float* var   = (const float*)d_in[12];
    float* out = (float*)d_out;

    static bool attr_set = false;
    if (!attr_set) {
        cudaFuncSetAttribute(k_mma<0>, cudaFuncAttributeMaxDynamicSharedMemorySize, SMEM_SZ0);
        cudaFuncSetAttribute(k_mma<1>, cudaFuncAttributeMaxDynamicSharedMemorySize, SMEM_SZ1);
        attr_set = true;
    }

    k0_prep<<<(1024 * 256 + 255) / 256, 256>>>(Wq, bq, Wk, bk, Wv, bv, bf, gamma, beta, mean, var);
    k_convx<<<dim3(128, 4, B_), 256>>>(x);
    k_mma<0><<<dim3(32, 8, B_), 256, SMEM_SZ0>>>(nullptr);
    k2s<<<256, 128>>>();
    k3a_kv<<<dim3(8, 64), 256>>>();
    k3b_kvnorm<<<64, 256>>>(Wf);
    k4_gate<<<64, 1024>>>();
    k_mma<1><<<dim3(32, 2, B_), 256, SMEM_SZ1>>>(out);
}